// round 5
// baseline (speedup 1.0000x reference)
#include <cuda_runtime.h>
#include <cuda_bf16.h>

#define NB  4096
#define ND  64
#define NDM 256
#define NK  32
#define NKA 16

// ----- device scratch (no runtime allocation allowed) -----
__device__ float g_M5[5*ND*NDM];       // folded matvec matrices [i][j]
__device__ float g_B6[6*NDM];          // folded biases (row 5 = 0)
__device__ float g_KC[NK*NDM], g_VC[NK*NDM], g_AKC[NKA*NDM], g_AVC[NKA*NDM];
__device__ float g_an2[NK], g_aan2[NKA];
__device__ float g_M2T2[ND*NDM];       // (Wo@form_W)^T : [d][j]
__device__ float g_G[ND*ND];           // form_W^T form_W
__device__ float g_Ceff[NB*ND];
__device__ float g_FbC[NB];
__device__ float g_inv_sigma;
__device__ float g_OutR[6u*NB*NDM];    // Q,KL,VL,KCd,VCd,U rows (25 MB)

__device__ __forceinline__ float wsum(float v){
  #pragma unroll
  for(int o=16;o>0;o>>=1) v += __shfl_xor_sync(0xffffffffu,v,o);
  return v;
}
__device__ __forceinline__ float wmax(float v){
  #pragma unroll
  for(int o=16;o>0;o>>=1) v = fmaxf(v,__shfl_xor_sync(0xffffffffu,v,o));
  return v;
}

// =============== P: all folded constants ===============
__global__ __launch_bounds__(256) void p_kernel(
  const float* __restrict__ zW,   const float* __restrict__ latW, const float* __restrict__ codeW,
  const float* __restrict__ Wq,   const float* __restrict__ Wk,   const float* __restrict__ Wv,
  const float* __restrict__ Wo,   const float* __restrict__ cemb, const float* __restrict__ acemb,
  const float* __restrict__ formW,const float* __restrict__ zb,   const float* __restrict__ latb,
  const float* __restrict__ codeb,const float* __restrict__ canch,const float* __restrict__ acanch,
  const float* __restrict__ ctrl, const float* __restrict__ ecov, const float* __restrict__ formb)
{
  int blk = blockIdx.x;
  const int t = threadIdx.x;

  if (blk < 80) {                 // five folded [64,256] matrices A@W
    int m = blk>>4, r0 = (blk&15)*4;
    const float* A  = (m==0)? zW : (m<3 ? latW : codeW);
    const float* Bm = (m==0)? Wq : ((m==1||m==3)? Wk : Wv);
    float* O = g_M5 + m*(ND*NDM);
    float a0=0,a1=0,a2=0,a3=0;
    for (int i=0;i<NDM;i++){
      float bv = Bm[i*NDM+t];
      a0 += A[(r0+0)*NDM+i]*bv; a1 += A[(r0+1)*NDM+i]*bv;
      a2 += A[(r0+2)*NDM+i]*bv; a3 += A[(r0+3)*NDM+i]*bv;
    }
    O[(r0+0)*NDM+t]=a0; O[(r0+1)*NDM+t]=a1; O[(r0+2)*NDM+t]=a2; O[(r0+3)*NDM+t]=a3;
    return;
  }
  blk -= 80;
  if (blk < 24) {                 // chart K/V tables
    int r0 = blk*4;
    const float* A; const float* Bm; float* O; int l0;
    if (r0 < 32)      { A=cemb;  Bm=Wk; O=g_KC;  l0=r0;    }
    else if (r0 < 64) { A=cemb;  Bm=Wv; O=g_VC;  l0=r0-32; }
    else if (r0 < 80) { A=acemb; Bm=Wk; O=g_AKC; l0=r0-64; }
    else              { A=acemb; Bm=Wv; O=g_AVC; l0=r0-80; }
    float a0=0,a1=0,a2=0,a3=0;
    for (int i=0;i<NDM;i++){
      float bv = Bm[i*NDM+t];
      a0 += A[(l0+0)*NDM+i]*bv; a1 += A[(l0+1)*NDM+i]*bv;
      a2 += A[(l0+2)*NDM+i]*bv; a3 += A[(l0+3)*NDM+i]*bv;
    }
    O[(l0+0)*NDM+t]=a0; O[(l0+1)*NDM+t]=a1; O[(l0+2)*NDM+t]=a2; O[(l0+3)*NDM+t]=a3;
    return;
  }
  blk -= 24;
  if (blk < 64) {                 // M2T2[d][j] = sum_i Wo[j][i]*formW[i][d]
    int j = blk*4 + (t>>6), d = t&63;
    float a = 0.f;
    for (int i=0;i<NDM;i++) a += Wo[j*NDM+i]*formW[i*ND+d];
    g_M2T2[d*NDM+j] = a;
    return;
  }
  blk -= 64;
  if (blk < 16) {                 // G = formW^T formW
    int idx = blk*256 + t, p = idx>>6, q = idx&63;
    float s = 0.f;
    for (int i=0;i<NDM;i++) s += formW[i*ND+p]*formW[i*ND+q];
    g_G[idx] = s;
    return;
  }
  blk -= 16;
  if (blk < 5) {                  // folded bias vectors
    const float* vv = (blk==0)? zb : (blk<3 ? latb : codeb);
    const float* Bm = (blk==0)? Wq : ((blk==1||blk==3)? Wk : Wv);
    float s = 0.f;
    for (int i=0;i<NDM;i++) s += vv[i]*Bm[i*NDM+t];
    g_B6[blk*NDM+t] = s;
    return;
  }
  blk -= 5;
  if (blk < 1) {                  // anchor norms + zero bias row 5
    if (t < 32) {
      float s=0.f;
      for (int i=0;i<ND;i++){ float v=canch[t*ND+i]; s+=v*v; }
      g_an2[t]=s;
    } else if (t < 48) {
      int k=t-32; float s=0.f;
      for (int i=0;i<ND;i++){ float v=acanch[k*ND+i]; s+=v*v; }
      g_aan2[k]=s;
    }
    g_B6[5*NDM+t] = 0.f;
    return;
  }
  blk -= 1;
  {                               // 64 blocks: ceff + form_b.ceff
    int w = t>>5, lane = t&31;
    #pragma unroll 1
    for (int rr=0; rr<8; rr++){
      int row = blk*64 + w*8 + rr;
      float e0=ecov[row*ND+lane], e1=ecov[row*ND+32+lane];
      float c0=ctrl[row*ND+lane], c1=ctrl[row*ND+32+lane];
      float ee = wsum(e0*e0+e1*e1);
      float ec = wsum(e0*c0+e1*c1);
      float k  = (ee > 1e-8f) ? ec/fmaxf(ee,1e-8f) : 0.f;
      float f0 = c0 - k*e0, f1 = c1 - k*e1;
      g_Ceff[row*ND+lane]    = f0;
      g_Ceff[row*ND+32+lane] = f1;
      float fb = wsum(formb[lane]*f0 + formb[lane+32]*f1);
      if (!lane) g_FbC[row] = fb;
    }
  }
}

// =============== S: spectral norm of form_W ===============
__global__ __launch_bounds__(256) void s_kernel(){
  __shared__ float sA[4096], sB[4096], sv[64];
  const int t = threadIdx.x;
  #pragma unroll
  for (int r=0;r<16;r++) sA[t+r*256] = g_G[t+r*256];
  __syncthreads();
  for (int sq=0; sq<3; sq++){              // sA <- sA*sA  (G^8)
    #pragma unroll 1
    for (int o=0;o<16;o++){
      int idx=t+o*256, p=idx>>6, r=idx&63;
      float s=0.f;
      for (int q=0;q<64;q++) s += sA[p*64+q]*sA[q*64+r];
      sB[idx]=s;
    }
    __syncthreads();
    for (int o=0;o<16;o++) sA[t+o*256]=sB[t+o*256];
    __syncthreads();
  }
  if (t < 32) {
    int lane=t;
    sv[lane]=1.f; sv[lane+32]=1.f; __syncwarp();
    for (int it=0; it<20; it++){
      float y0=0.f, y1=0.f;
      for (int q=0;q<64;q++){ float vq=sv[q]; y0+=sA[q*64+lane]*vq; y1+=sA[q*64+32+lane]*vq; }
      float rn = rsqrtf(wsum(y0*y0+y1*y1));
      sv[lane]=y0*rn; sv[lane+32]=y1*rn; __syncwarp();
    }
    float p0=0.f, p1=0.f;                  // Rayleigh on ORIGINAL G
    for (int q=0;q<64;q++){ float vq=sv[q]; p0+=g_G[lane*64+q]*vq; p1+=g_G[(lane+32)*64+q]*vq; }
    float lam = wsum(p0*sv[lane]+p1*sv[lane+32]);
    if (!lane) g_inv_sigma = 1.f/fmaxf(sqrtf(fmaxf(lam,0.f)),1e-8f);
  }
}

// =============== G1: six [4096,64]@[64,256] GEMMs ===============
__global__ __launch_bounds__(256) void g1_kernel(
  const float* __restrict__ z, const float* __restrict__ az, const float* __restrict__ acz)
{
  __shared__ __align__(16) float xsT[64*68];
  const int t = threadIdx.x, y = blockIdx.y, b0 = blockIdx.x*64;
  const float* X = (y==0)? z : (y<=2)? az : (y<=4)? acz : g_Ceff;
  const float* M = (y<5) ? (g_M5 + y*(ND*NDM)) : g_M2T2;
  #pragma unroll
  for (int r=0;r<16;r++){
    int idx=t+r*256, bb=idx>>6, ii=idx&63;
    xsT[ii*68+bb] = X[(b0+bb)*ND+ii];
  }
  __syncthreads();
  float acc[64];
  #pragma unroll
  for (int i=0;i<64;i++) acc[i]=0.f;
  #pragma unroll 1
  for (int i=0;i<ND;i++){
    float mv = M[i*NDM+t];
    const float4* x4 = reinterpret_cast<const float4*>(xsT + i*68);
    #pragma unroll
    for (int b4=0;b4<16;b4++){
      float4 xv = x4[b4];
      acc[4*b4+0]+=xv.x*mv; acc[4*b4+1]+=xv.y*mv;
      acc[4*b4+2]+=xv.z*mv; acc[4*b4+3]+=xv.w*mv;
    }
  }
  float bj = g_B6[y*NDM+t];
  float* op = g_OutR + ((size_t)y*NB + b0)*NDM + t;
  #pragma unroll 1
  for (int bb=0;bb<64;bb++) op[(size_t)bb*NDM] = acc[bb] + bj;
}

// =============== F: fused attention + epilogue (warp per batch) ===============
__global__ __launch_bounds__(256) void f_kernel(
  const float* __restrict__ z,   const float* __restrict__ rw,
  const float* __restrict__ az,  const float* __restrict__ arw,
  const float* __restrict__ acz, const float* __restrict__ canch,
  const float* __restrict__ acanch, float* __restrict__ out)
{
  __shared__ float sSC[8][52];
  const int w = threadIdx.x>>5, lane = threadIdx.x&31;
  const int b = blockIdx.x*8 + w;

  const float* Q   = g_OutR + (size_t)b*NDM;
  const float* KL  = g_OutR + ((size_t)1*NB + b)*NDM;
  const float* VL  = g_OutR + ((size_t)2*NB + b)*NDM;
  const float* KCd = g_OutR + ((size_t)3*NB + b)*NDM;
  const float* VCd = g_OutR + ((size_t)4*NB + b)*NDM;
  const float* Ub  = g_OutR + ((size_t)5*NB + b)*NDM;

  float qr[8], vlat[8], vcode[8];
  #pragma unroll
  for (int t=0;t<8;t++) qr[t] = Q[lane+32*t];

  float z0 = z[b*ND+lane],   z1 = z[b*ND+32+lane];
  float a0 = az[b*ND+lane],  a1 = az[b*ND+32+lane];
  float c0 = acz[b*ND+lane], c1 = acz[b*ND+32+lane];
  float z2 = wsum(z0*z0 + z1*z1);

  { // token 0: latent
    float p=0.f;
    #pragma unroll
    for (int t=0;t<8;t++){ p += qr[t]*KL[lane+32*t]; vlat[t] = VL[lane+32*t]; }
    float d0=z0-a0, d1=z1-a1;
    float s = wsum(p*0.0625f - d0*d0 - d1*d1);
    if (!lane) sSC[w][0]=s;
  }
  { // token 1: code
    float p=0.f;
    #pragma unroll
    for (int t=0;t<8;t++){ p += qr[t]*KCd[lane+32*t]; vcode[t] = VCd[lane+32*t]; }
    float d0=z0-c0, d1=z1-c1;
    float s = wsum(p*0.0625f - d0*d0 - d1*d1);
    if (!lane) sSC[w][1]=s;
  }
  #pragma unroll 1
  for (int k=0;k<NKA;k++){     // action charts
    const float* kp = g_AKC + k*NDM;
    float p=0.f;
    #pragma unroll
    for (int t=0;t<8;t++) p += qr[t]*kp[lane+32*t];
    float aw = arw[b*NKA+k];
    float par = p*(aw*0.0625f)
              + 2.f*(z0*acanch[k*ND+lane] + z1*acanch[k*ND+32+lane]);
    float s = wsum(par) - z2 - g_aan2[k];
    if (!lane) sSC[w][2+k]=s;
  }
  #pragma unroll 1
  for (int k=0;k<NK;k++){      // charts
    const float* kp = g_KC + k*NDM;
    float p=0.f;
    #pragma unroll
    for (int t=0;t<8;t++) p += qr[t]*kp[lane+32*t];
    float cw = rw[b*NK+k];
    float par = p*(cw*0.0625f)
              + 2.f*(z0*canch[k*ND+lane] + z1*canch[k*ND+32+lane]);
    float s = wsum(par) - z2 - g_an2[k];
    if (!lane) sSC[w][18+k]=s;
  }
  __syncwarp();

  float mx = -1e30f;
  for (int s=lane; s<50; s+=32) mx = fmaxf(mx, sSC[w][s]);
  mx = wmax(mx);
  float se = 0.f;
  for (int s=lane; s<50; s+=32) se += __expf(sSC[w][s]-mx);
  se = wsum(se);
  float inv = 1.f/se;
  for (int s=lane; s<50; s+=32){
    float mult = 1.f;
    if (s >= 18)     mult = rw[b*NK + (s-18)];
    else if (s >= 2) mult = arw[b*NKA + (s-2)];
    sSC[w][s] = __expf(sSC[w][s]-mx)*inv*mult;   // attn weight * rw-folding
  }
  __syncwarp();

  float w0 = sSC[w][0], w1 = sSC[w][1];
  float facc[8];
  #pragma unroll
  for (int t=0;t<8;t++) facc[t] = w0*vlat[t] + w1*vcode[t];
  #pragma unroll 1
  for (int k=0;k<NKA;k++){
    float wv = sSC[w][2+k]; const float* vp = g_AVC + k*NDM;
    #pragma unroll
    for (int t=0;t<8;t++) facc[t] += wv*vp[lane+32*t];
  }
  #pragma unroll 1
  for (int k=0;k<NK;k++){
    float wv = sSC[w][18+k]; const float* vp = g_VC + k*NDM;
    #pragma unroll
    for (int t=0;t<8;t++) facc[t] += wv*vp[lane+32*t];
  }
  float acc = 0.f;
  #pragma unroll
  for (int t=0;t<8;t++) acc += facc[t]*Ub[lane+32*t];
  acc = wsum(acc);
  if (!lane) out[b] = g_inv_sigma*acc + g_FbC[b];
}

// =============== launch ===============
extern "C" void kernel_launch(void* const* d_in, const int* in_sizes, int n_in,
                              void* d_out, int out_size)
{
  const float* z     =(const float*)d_in[0];
  const float* rw    =(const float*)d_in[1];
  const float* az    =(const float*)d_in[2];
  const float* arw   =(const float*)d_in[3];
  const float* acz   =(const float*)d_in[4];
  const float* ctrl  =(const float*)d_in[5];
  const float* ecov  =(const float*)d_in[6];
  const float* cemb  =(const float*)d_in[7];
  const float* canch =(const float*)d_in[8];
  const float* acemb =(const float*)d_in[9];
  const float* acanch=(const float*)d_in[10];
  const float* zW    =(const float*)d_in[11];
  const float* zb    =(const float*)d_in[12];
  const float* latW  =(const float*)d_in[13];
  const float* latb  =(const float*)d_in[14];
  const float* codeW =(const float*)d_in[15];
  const float* codeb =(const float*)d_in[16];
  const float* Wq    =(const float*)d_in[17];
  const float* Wk    =(const float*)d_in[18];
  const float* Wv    =(const float*)d_in[19];
  const float* Wo    =(const float*)d_in[20];
  const float* formW =(const float*)d_in[21];
  const float* formb =(const float*)d_in[22];
  float* out = (float*)d_out;

  p_kernel<<<254,256>>>(zW,latW,codeW,Wq,Wk,Wv,Wo,cemb,acemb,formW,
                        zb,latb,codeb,canch,acanch,ctrl,ecov,formb);
  s_kernel<<<1,256>>>();
  g1_kernel<<<dim3(64,6),256>>>(z,az,acz);
  f_kernel<<<512,256>>>(z,rw,az,arw,acz,canch,acanch,out);
}

// round 6
// speedup vs baseline: 1.5658x; 1.5658x over previous
#include <cuda_runtime.h>
#include <cuda_bf16.h>

#define NB  4096
#define ND  64
#define NDM 256
#define NK  32
#define NKA 16
#define NC  160   // G2 output columns per matrix

// ----- device scratch -----
__device__ float g_M5[5*ND*NDM];       // Zq, Lk, Lv, Ck, Cv
__device__ float g_B6[6*NDM];          // bq, bLk, bLv, bCk, bCv, 0
__device__ float g_KC[NK*NDM], g_VC[NK*NDM], g_AKC[NKA*NDM], g_AVC[NKA*NDM];
__device__ float g_an2[NK], g_aan2[NKA];
__device__ float g_M2T2[ND*NDM];       // (Wo@form_W)^T : [d][j]
__device__ float g_G[ND*ND];           // form_W^T form_W
__device__ float g_Ceff[NB*ND];
__device__ float g_FbC[NB];
__device__ float g_inv_sigma;
__device__ float g_M4[4*ND*NC];        // folded GEMM matrices [y][i][j]
__device__ float g_bz[4*NC];           // GEMM biases
__device__ float g_Gout[4u*NB*NC];     // GEMM outputs (10.5 MB)

__device__ __forceinline__ float wsum(float v){
  #pragma unroll
  for(int o=16;o>0;o>>=1) v += __shfl_xor_sync(0xffffffffu,v,o);
  return v;
}
__device__ __forceinline__ float wmax(float v){
  #pragma unroll
  for(int o=16;o>0;o>>=1) v = fmaxf(v,__shfl_xor_sync(0xffffffffu,v,o));
  return v;
}

// =============== P1: stage-1 folds (verbatim from R5 passing version) ===============
__global__ __launch_bounds__(256) void p_kernel(
  const float* __restrict__ zW,   const float* __restrict__ latW, const float* __restrict__ codeW,
  const float* __restrict__ Wq,   const float* __restrict__ Wk,   const float* __restrict__ Wv,
  const float* __restrict__ Wo,   const float* __restrict__ cemb, const float* __restrict__ acemb,
  const float* __restrict__ formW,const float* __restrict__ zb,   const float* __restrict__ latb,
  const float* __restrict__ codeb,const float* __restrict__ canch,const float* __restrict__ acanch,
  const float* __restrict__ ctrl, const float* __restrict__ ecov, const float* __restrict__ formb)
{
  int blk = blockIdx.x;
  const int t = threadIdx.x;

  if (blk < 80) {                 // five folded [64,256] matrices A@W
    int m = blk>>4, r0 = (blk&15)*4;
    const float* A  = (m==0)? zW : (m<3 ? latW : codeW);
    const float* Bm = (m==0)? Wq : ((m==1||m==3)? Wk : Wv);
    float* O = g_M5 + m*(ND*NDM);
    float a0=0,a1=0,a2=0,a3=0;
    for (int i=0;i<NDM;i++){
      float bv = Bm[i*NDM+t];
      a0 += A[(r0+0)*NDM+i]*bv; a1 += A[(r0+1)*NDM+i]*bv;
      a2 += A[(r0+2)*NDM+i]*bv; a3 += A[(r0+3)*NDM+i]*bv;
    }
    O[(r0+0)*NDM+t]=a0; O[(r0+1)*NDM+t]=a1; O[(r0+2)*NDM+t]=a2; O[(r0+3)*NDM+t]=a3;
    return;
  }
  blk -= 80;
  if (blk < 24) {                 // chart K/V tables
    int r0 = blk*4;
    const float* A; const float* Bm; float* O; int l0;
    if (r0 < 32)      { A=cemb;  Bm=Wk; O=g_KC;  l0=r0;    }
    else if (r0 < 64) { A=cemb;  Bm=Wv; O=g_VC;  l0=r0-32; }
    else if (r0 < 80) { A=acemb; Bm=Wk; O=g_AKC; l0=r0-64; }
    else              { A=acemb; Bm=Wv; O=g_AVC; l0=r0-80; }
    float a0=0,a1=0,a2=0,a3=0;
    for (int i=0;i<NDM;i++){
      float bv = Bm[i*NDM+t];
      a0 += A[(l0+0)*NDM+i]*bv; a1 += A[(l0+1)*NDM+i]*bv;
      a2 += A[(l0+2)*NDM+i]*bv; a3 += A[(l0+3)*NDM+i]*bv;
    }
    O[(l0+0)*NDM+t]=a0; O[(l0+1)*NDM+t]=a1; O[(l0+2)*NDM+t]=a2; O[(l0+3)*NDM+t]=a3;
    return;
  }
  blk -= 24;
  if (blk < 64) {                 // M2T2[d][j] = sum_i Wo[j][i]*formW[i][d]
    int j = blk*4 + (t>>6), d = t&63;
    float a = 0.f;
    for (int i=0;i<NDM;i++) a += Wo[j*NDM+i]*formW[i*ND+d];
    g_M2T2[d*NDM+j] = a;
    return;
  }
  blk -= 64;
  if (blk < 16) {                 // G = formW^T formW
    int idx = blk*256 + t, p = idx>>6, q = idx&63;
    float s = 0.f;
    for (int i=0;i<NDM;i++) s += formW[i*ND+p]*formW[i*ND+q];
    g_G[idx] = s;
    return;
  }
  blk -= 16;
  if (blk < 5) {                  // folded bias vectors
    const float* vv = (blk==0)? zb : (blk<3 ? latb : codeb);
    const float* Bm = (blk==0)? Wq : ((blk==1||blk==3)? Wk : Wv);
    float s = 0.f;
    for (int i=0;i<NDM;i++) s += vv[i]*Bm[i*NDM+t];
    g_B6[blk*NDM+t] = s;
    return;
  }
  blk -= 5;
  if (blk < 1) {                  // anchor norms
    if (t < 32) {
      float s=0.f;
      for (int i=0;i<ND;i++){ float v=canch[t*ND+i]; s+=v*v; }
      g_an2[t]=s;
    } else if (t < 48) {
      int k=t-32; float s=0.f;
      for (int i=0;i<ND;i++){ float v=acanch[k*ND+i]; s+=v*v; }
      g_aan2[k]=s;
    }
    g_B6[5*NDM+t] = 0.f;
    return;
  }
  blk -= 1;
  {                               // 64 blocks: ceff + form_b.ceff
    int w = t>>5, lane = t&31;
    #pragma unroll 1
    for (int rr=0; rr<8; rr++){
      int row = blk*64 + w*8 + rr;
      float e0=ecov[row*ND+lane], e1=ecov[row*ND+32+lane];
      float c0=ctrl[row*ND+lane], c1=ctrl[row*ND+32+lane];
      float ee = wsum(e0*e0+e1*e1);
      float ec = wsum(e0*c0+e1*c1);
      float k  = (ee > 1e-8f) ? ec/fmaxf(ee,1e-8f) : 0.f;
      float f0 = c0 - k*e0, f1 = c1 - k*e1;
      g_Ceff[row*ND+lane]    = f0;
      g_Ceff[row*ND+32+lane] = f1;
      float fb = wsum(formb[lane]*f0 + formb[lane+32]*f1);
      if (!lane) g_FbC[row] = fb;
    }
  }
}

// =============== P2S: stage-2 folds + sigma ===============
// blocks 0..255: M4[y][i][:] rows.  block 256: bias rows.  block 257: sigma.
__global__ __launch_bounds__(256) void p2s_kernel(
  const float* __restrict__ canch, const float* __restrict__ acanch)
{
  __shared__ float sA[4096], sB[4096], sv[64];
  const int b_ = blockIdx.x, t = threadIdx.x;
  const float* Zq = g_M5;
  const float* Lk = g_M5 + 1*ND*NDM;
  const float* Lv = g_M5 + 2*ND*NDM;
  const float* Ck = g_M5 + 3*ND*NDM;
  const float* Cv = g_M5 + 4*ND*NDM;
  const float* bq = g_B6;

  if (b_ < 256){
    int y = b_>>6, i = b_&63, j = t;
    if (j >= NC) return;
    float val = 0.f;
    if (y==0){
      if (j < 48){                                  // z @ (Zq@KCall^T)
        const float* B = (j<16)? (g_AKC + j*NDM) : (g_KC + (j-16)*NDM);
        const float* A = Zq + i*NDM;
        float s=0.f; for(int q=0;q<NDM;q++) s += A[q]*B[q];
        val = s;
      } else if (j < 96){                           // anchor columns
        val = (j<64)? acanch[(j-48)*ND + i] : canch[(j-64)*ND + i];
      } else if (j < 98){                           // u1 = Zq@bLk, u2 = Zq@bCk
        const float* B = (j==96)? (g_B6+1*NDM) : (g_B6+3*NDM);
        const float* A = Zq + i*NDM;
        float s=0.f; for(int q=0;q<NDM;q++) s += A[q]*B[q];
        val = s;
      }
    } else if (y<=2){                               // az / acz matrices (row p = i)
      const float* Kf = (y==1)? Lk : Ck;
      const float* Vf = (y==1)? Lv : Cv;
      if (j < 64){                                  // B1^T: M[p][j] = sum Zq[j]·Kf[p]
        const float* A = Zq + j*NDM;
        const float* B = Kf + i*NDM;
        float s=0.f; for(int q=0;q<NDM;q++) s += A[q]*B[q];
        val = s;
      } else if (j < 128){                          // B3[p][d] = Vf[p]·M2T2[d]
        const float* A = g_M2T2 + (j-64)*NDM;
        const float* B = Vf + i*NDM;
        float s=0.f; for(int q=0;q<NDM;q++) s += A[q]*B[q];
        val = s;
      } else if (j == 128){                         // w = Kf[p]·bq
        const float* A = Kf + i*NDM;
        float s=0.f; for(int q=0;q<NDM;q++) s += A[q]*bq[q];
        val = s;
      }
    } else {                                        // y==3: Ceff matrix (row d = i)
      if (j < 48){                                  // Wt[d][k] = M2T2[d]·VCall[k]
        const float* B = (j<16)? (g_AVC + j*NDM) : (g_VC + (j-16)*NDM);
        const float* A = g_M2T2 + i*NDM;
        float s=0.f; for(int q=0;q<NDM;q++) s += A[q]*B[q];
        val = s;
      } else if (j < 50){                           // vb3 = M2T2[d]·bLv, vb4 = ·bCv
        const float* B = (j==48)? (g_B6+2*NDM) : (g_B6+4*NDM);
        const float* A = g_M2T2 + i*NDM;
        float s=0.f; for(int q=0;q<NDM;q++) s += A[q]*B[q];
        val = s;
      }
    }
    g_M4[(y*ND + i)*NC + j] = val;
    return;
  }
  if (b_ == 256){                                   // bias rows
    if (t < NC){
      float v0 = 0.f;
      if (t < 48){
        const float* B = (t<16)? (g_AKC + t*NDM) : (g_KC + (t-16)*NDM);
        float s=0.f; for(int q=0;q<NDM;q++) s += bq[q]*B[q]; v0=s;
      } else if (t == 96){
        const float* B = g_B6+1*NDM;                // c1 = bq·bLk
        float s=0.f; for(int q=0;q<NDM;q++) s += bq[q]*B[q]; v0=s;
      } else if (t == 97){
        const float* B = g_B6+3*NDM;                // c2 = bq·bCk
        float s=0.f; for(int q=0;q<NDM;q++) s += bq[q]*B[q]; v0=s;
      }
      g_bz[t] = v0;
      g_bz[NC+t]=0.f; g_bz[2*NC+t]=0.f; g_bz[3*NC+t]=0.f;
    }
    return;
  }
  // b_ == 257 : sigma (validated in R5)
  #pragma unroll
  for (int r=0;r<16;r++) sA[t+r*256] = g_G[t+r*256];
  __syncthreads();
  for (int sq=0; sq<3; sq++){
    #pragma unroll 1
    for (int o=0;o<16;o++){
      int idx=t+o*256, p=idx>>6, r=idx&63;
      float s=0.f;
      for (int q=0;q<64;q++) s += sA[p*64+q]*sA[q*64+r];
      sB[idx]=s;
    }
    __syncthreads();
    for (int o=0;o<16;o++) sA[t+o*256]=sB[t+o*256];
    __syncthreads();
  }
  if (t < 32) {
    int lane=t;
    sv[lane]=1.f; sv[lane+32]=1.f; __syncwarp();
    for (int it=0; it<20; it++){
      float y0=0.f, y1=0.f;
      for (int q=0;q<64;q++){ float vq=sv[q]; y0+=sA[q*64+lane]*vq; y1+=sA[q*64+32+lane]*vq; }
      float rn = rsqrtf(wsum(y0*y0+y1*y1));
      sv[lane]=y0*rn; sv[lane+32]=y1*rn; __syncwarp();
    }
    float p0=0.f, p1=0.f;
    for (int q=0;q<64;q++){ float vq=sv[q]; p0+=g_G[lane*64+q]*vq; p1+=g_G[(lane+32)*64+q]*vq; }
    float lam = wsum(p0*sv[lane]+p1*sv[lane+32]);
    if (!lane) g_inv_sigma = 1.f/fmaxf(sqrtf(fmaxf(lam,0.f)),1e-8f);
  }
}

// =============== G2: four [4096,64]@[64,160] GEMMs ===============
__global__ __launch_bounds__(NC) void g2_kernel(
  const float* __restrict__ z, const float* __restrict__ az, const float* __restrict__ acz)
{
  __shared__ __align__(16) float xsT[64*68];
  const int t = threadIdx.x, y = blockIdx.y, b0 = blockIdx.x*64;
  const float* X = (y==0)? z : (y==1)? az : (y==2)? acz : g_Ceff;
  const float* M = g_M4 + y*ND*NC;
  for (int idx=t; idx<4096; idx+=NC){
    int bb = idx>>6, ii = idx&63;
    xsT[ii*68+bb] = X[(b0+bb)*ND+ii];
  }
  __syncthreads();
  float acc[64];
  #pragma unroll
  for (int i=0;i<64;i++) acc[i]=0.f;
  #pragma unroll 1
  for (int i=0;i<ND;i++){
    float mv = M[i*NC+t];
    const float4* x4 = reinterpret_cast<const float4*>(xsT + i*68);
    #pragma unroll
    for (int b4=0;b4<16;b4++){
      float4 xv = x4[b4];
      acc[4*b4+0]+=xv.x*mv; acc[4*b4+1]+=xv.y*mv;
      acc[4*b4+2]+=xv.z*mv; acc[4*b4+3]+=xv.w*mv;
    }
  }
  float bj = g_bz[y*NC+t];
  float* op = g_Gout + ((size_t)y*NB + b0)*NC + t;
  #pragma unroll 1
  for (int bb=0;bb<64;bb++) op[(size_t)bb*NC] = acc[bb] + bj;
}

// =============== F: fused scores + softmax + epilogue (warp per batch) ===============
__global__ __launch_bounds__(256) void f_kernel(
  const float* __restrict__ z,  const float* __restrict__ rw,
  const float* __restrict__ az, const float* __restrict__ arw,
  const float* __restrict__ acz, float* __restrict__ out)
{
  const int w = threadIdx.x>>5, lane = threadIdx.x&31;
  const int b = blockIdx.x*8 + w;

  const float* gz   = g_Gout + (size_t)b*NC;
  const float* gaz  = g_Gout + ((size_t)NB + b)*NC;
  const float* gacz = g_Gout + ((size_t)2*NB + b)*NC;
  const float* gc   = g_Gout + ((size_t)3*NB + b)*NC;

  float z0  = z[b*ND+lane],   z1  = z[b*ND+32+lane];
  float a0  = az[b*ND+lane],  a1  = az[b*ND+32+lane];
  float c0  = acz[b*ND+lane], c1  = acz[b*ND+32+lane];
  float ce0 = g_Ceff[b*ND+lane], ce1 = g_Ceff[b*ND+32+lane];

  // 9 warp dots of 64
  float d_z2   = wsum(z0*z0 + z1*z1);
  float d_zaz  = wsum(z0*a0 + z1*a1);
  float d_az2  = wsum(a0*a0 + a1*a1);
  float d_zacz = wsum(z0*c0 + z1*c1);
  float d_acz2 = wsum(c0*c0 + c1*c1);
  float y1a = gaz[lane],  y1b = gaz[32+lane];
  float d_zy1  = wsum(z0*y1a + z1*y1b);
  float y2a = gacz[lane], y2b = gacz[32+lane];
  float d_zy2  = wsum(z0*y2a + z1*y2b);
  float y3a = gaz[64+lane],  y3b = gaz[96+lane];
  float d_cy3  = wsum(ce0*y3a + ce1*y3b);
  float y4a = gacz[64+lane], y4b = gacz[96+lane];
  float d_cy4  = wsum(ce0*y4a + ce1*y4b);

  // lane handles tokens (lane) and (lane+32 if lane<18); tokens: 0 lat, 1 code,
  // 2..17 achart, 18..49 chart
  float s0, t0, s1 = -1e30f, t1 = 0.f;
  {
    int tok = lane;
    if (tok == 0){
      s0 = (d_zy1 + gz[96] + gaz[128])*0.0625f - (d_z2 - 2.f*d_zaz + d_az2);
      t0 = d_cy3 + gc[48];
    } else if (tok == 1){
      s0 = (d_zy2 + gz[97] + gacz[128])*0.0625f - (d_z2 - 2.f*d_zacz + d_acz2);
      t0 = d_cy4 + gc[49];
    } else if (tok < 18){
      int k = tok-2; float aw = arw[b*NKA+k];
      s0 = aw*gz[k]*0.0625f - (d_z2 - 2.f*gz[48+k] + g_aan2[k]);
      t0 = aw*gc[k];
    } else {
      int k = tok-18; float cw = rw[b*NK+k];
      s0 = cw*gz[16+k]*0.0625f - (d_z2 - 2.f*gz[64+k] + g_an2[k]);
      t0 = cw*gc[16+k];
    }
  }
  if (lane < 18){
    int k = lane + 14;   // token lane+32 = chart k = lane+14
    float cw = rw[b*NK+k];
    s1 = cw*gz[16+k]*0.0625f - (d_z2 - 2.f*gz[64+k] + g_an2[k]);
    t1 = cw*gc[16+k];
  }

  float m = wmax(fmaxf(s0, s1));
  float e0 = __expf(s0 - m);
  float e1 = (lane < 18) ? __expf(s1 - m) : 0.f;
  float den = wsum(e0 + e1);
  float num = wsum(e0*t0 + e1*t1);
  if (!lane) out[b] = g_inv_sigma * num / den + g_FbC[b];
}

// =============== launch ===============
extern "C" void kernel_launch(void* const* d_in, const int* in_sizes, int n_in,
                              void* d_out, int out_size)
{
  const float* z     =(const float*)d_in[0];
  const float* rw    =(const float*)d_in[1];
  const float* az    =(const float*)d_in[2];
  const float* arw   =(const float*)d_in[3];
  const float* acz   =(const float*)d_in[4];
  const float* ctrl  =(const float*)d_in[5];
  const float* ecov  =(const float*)d_in[6];
  const float* cemb  =(const float*)d_in[7];
  const float* canch =(const float*)d_in[8];
  const float* acemb =(const float*)d_in[9];
  const float* acanch=(const float*)d_in[10];
  const float* zW    =(const float*)d_in[11];
  const float* zb    =(const float*)d_in[12];
  const float* latW  =(const float*)d_in[13];
  const float* latb  =(const float*)d_in[14];
  const float* codeW =(const float*)d_in[15];
  const float* codeb =(const float*)d_in[16];
  const float* Wq    =(const float*)d_in[17];
  const float* Wk    =(const float*)d_in[18];
  const float* Wv    =(const float*)d_in[19];
  const float* Wo    =(const float*)d_in[20];
  const float* formW =(const float*)d_in[21];
  const float* formb =(const float*)d_in[22];
  float* out = (float*)d_out;

  p_kernel<<<254,256>>>(zW,latW,codeW,Wq,Wk,Wv,Wo,cemb,acemb,formW,
                        zb,latb,codeb,canch,acanch,ctrl,ecov,formb);
  p2s_kernel<<<258,256>>>(canch,acanch);
  g2_kernel<<<dim3(64,4),NC>>>(z,az,acz);
  f_kernel<<<512,256>>>(z,rw,az,arw,acz,out);
}

// round 7
// speedup vs baseline: 1.6845x; 1.0758x over previous
#include <cuda_runtime.h>
#include <cuda_bf16.h>

#define NB  4096
#define ND  64
#define NDM 256
#define NK  32
#define NKA 16
#define NC  160   // G2 output stride (padded); active cols per y: 98,129,129,50

// ----- device scratch (16B aligned for float4) -----
__device__ __align__(16) float g_M5[5*ND*NDM];   // Zq, Lk, Lv, Ck, Cv
__device__ __align__(16) float g_B6[5*NDM];      // bq, bLk, bLv, bCk, bCv
__device__ __align__(16) float g_KC[NK*NDM], g_VC[NK*NDM];
__device__ __align__(16) float g_AKC[NKA*NDM], g_AVC[NKA*NDM];
__device__ float g_an2[NK], g_aan2[NKA];
__device__ __align__(16) float g_M2T2[ND*NDM];   // (Wo@form_W)^T : [d][j]
__device__ __align__(16) float g_G[ND*ND];       // form_W^T form_W
__device__ __align__(16) float g_Ceff[NB*ND];
__device__ float g_FbC[NB];
__device__ float g_inv_sigma;
__device__ __align__(16) float g_M4[4*ND*NC];    // folded GEMM matrices
__device__ __align__(16) float g_bz[4*NC];
__device__ __align__(16) float g_Gout[4u*NB*NC];

__device__ __forceinline__ float wsum(float v){
  #pragma unroll
  for(int o=16;o>0;o>>=1) v += __shfl_xor_sync(0xffffffffu,v,o);
  return v;
}
__device__ __forceinline__ float wmax(float v){
  #pragma unroll
  for(int o=16;o>0;o>>=1) v = fmaxf(v,__shfl_xor_sync(0xffffffffu,v,o));
  return v;
}
// warp dot of two 256-float vectors, both 16B aligned
__device__ __forceinline__ float dot256(const float* __restrict__ A,
                                        const float* __restrict__ B, int lane){
  float4 a0 = *(const float4*)(A + lane*8);
  float4 a1 = *(const float4*)(A + lane*8 + 4);
  float4 b0 = *(const float4*)(B + lane*8);
  float4 b1 = *(const float4*)(B + lane*8 + 4);
  float s = a0.x*b0.x + a0.y*b0.y + a0.z*b0.z + a0.w*b0.w
          + a1.x*b1.x + a1.y*b1.y + a1.z*b1.z + a1.w*b1.w;
  return wsum(s);
}

// =============== P1: stage-1 folds ===============
// blocks: [0,80) five matrices | [80,104) chart tables | [104,120) M2T2
// [120,136) G | [136,141) biases | 141 anchors | [142,206) ceff
__global__ __launch_bounds__(256) void p_kernel(
  const float* __restrict__ zW,   const float* __restrict__ latW, const float* __restrict__ codeW,
  const float* __restrict__ Wq,   const float* __restrict__ Wk,   const float* __restrict__ Wv,
  const float* __restrict__ Wo,   const float* __restrict__ cemb, const float* __restrict__ acemb,
  const float* __restrict__ formW,const float* __restrict__ zb,   const float* __restrict__ latb,
  const float* __restrict__ codeb,const float* __restrict__ canch,const float* __restrict__ acanch,
  const float* __restrict__ ctrl, const float* __restrict__ ecov, const float* __restrict__ formb)
{
  int blk = blockIdx.x;
  const int t = threadIdx.x;

  if (blk < 80) {                 // five folded [64,256] matrices A@W, thread = 1 row x 4 cols
    int m = blk>>4;
    int r = (blk&15)*4 + (t>>6);
    int c4 = (t&63)*4;
    const float* A  = (m==0)? zW : (m<3 ? latW : codeW);
    const float* Bm = (m==0)? Wq : ((m==1||m==3)? Wk : Wv);
    const float* Ar = A + r*NDM;
    float4 acc = make_float4(0.f,0.f,0.f,0.f);
    #pragma unroll 4
    for (int i=0;i<NDM;i++){
      float a = Ar[i];
      float4 bv = *(const float4*)(Bm + i*NDM + c4);
      acc.x += a*bv.x; acc.y += a*bv.y; acc.z += a*bv.z; acc.w += a*bv.w;
    }
    *(float4*)(g_M5 + m*(ND*NDM) + r*NDM + c4) = acc;
    return;
  }
  blk -= 80;
  if (blk < 24) {                 // chart tables: 96 combined rows, 4 rows/block
    int g = blk*4 + (t>>6);
    int c4 = (t&63)*4;
    const float* Ar; const float* Bm; float* O; int lr;
    if (g < 32)      { Ar=cemb  + g*NDM;      Bm=Wk; O=g_KC;  lr=g;    }
    else if (g < 64) { Ar=cemb  + (g-32)*NDM; Bm=Wv; O=g_VC;  lr=g-32; }
    else if (g < 80) { Ar=acemb + (g-64)*NDM; Bm=Wk; O=g_AKC; lr=g-64; }
    else             { Ar=acemb + (g-80)*NDM; Bm=Wv; O=g_AVC; lr=g-80; }
    float4 acc = make_float4(0.f,0.f,0.f,0.f);
    #pragma unroll 4
    for (int i=0;i<NDM;i++){
      float a = Ar[i];
      float4 bv = *(const float4*)(Bm + i*NDM + c4);
      acc.x += a*bv.x; acc.y += a*bv.y; acc.z += a*bv.z; acc.w += a*bv.w;
    }
    *(float4*)(O + lr*NDM + c4) = acc;
    return;
  }
  blk -= 24;
  if (blk < 16) {                 // M2T2[d][j] = sum_i Wo[j][i]*formW[i][d]
    int j = blk*16 + (t>>4);
    int d4 = (t&15)*4;
    float4 acc = make_float4(0.f,0.f,0.f,0.f);
    #pragma unroll 4
    for (int i=0;i<NDM;i++){
      float wv = Wo[j*NDM+i];
      float4 fv = *(const float4*)(formW + i*ND + d4);
      acc.x += wv*fv.x; acc.y += wv*fv.y; acc.z += wv*fv.z; acc.w += wv*fv.w;
    }
    g_M2T2[(d4+0)*NDM+j]=acc.x; g_M2T2[(d4+1)*NDM+j]=acc.y;
    g_M2T2[(d4+2)*NDM+j]=acc.z; g_M2T2[(d4+3)*NDM+j]=acc.w;
    return;
  }
  blk -= 16;
  if (blk < 16) {                 // G = formW^T formW
    int idx = blk*256 + t, p = idx>>6, q = idx&63;
    float s = 0.f;
    #pragma unroll 4
    for (int i=0;i<NDM;i++) s += formW[i*ND+p]*formW[i*ND+q];
    g_G[idx] = s;
    return;
  }
  blk -= 16;
  if (blk < 5) {                  // folded bias vectors
    const float* vv = (blk==0)? zb : (blk<3 ? latb : codeb);
    const float* Bm = (blk==0)? Wq : ((blk==1||blk==3)? Wk : Wv);
    float s = 0.f;
    #pragma unroll 4
    for (int i=0;i<NDM;i++) s += vv[i]*Bm[i*NDM+t];
    g_B6[blk*NDM+t] = s;
    return;
  }
  blk -= 5;
  if (blk < 1) {                  // anchor norms
    if (t < 32) {
      float s=0.f;
      for (int i=0;i<ND;i++){ float v=canch[t*ND+i]; s+=v*v; }
      g_an2[t]=s;
    } else if (t < 48) {
      int k=t-32; float s=0.f;
      for (int i=0;i<ND;i++){ float v=acanch[k*ND+i]; s+=v*v; }
      g_aan2[k]=s;
    }
    return;
  }
  blk -= 1;
  {                               // 64 blocks: ceff + form_b.ceff
    int w = t>>5, lane = t&31;
    #pragma unroll 1
    for (int rr=0; rr<8; rr++){
      int row = blk*64 + w*8 + rr;
      float e0=ecov[row*ND+lane], e1=ecov[row*ND+32+lane];
      float c0=ctrl[row*ND+lane], c1=ctrl[row*ND+32+lane];
      float ee = wsum(e0*e0+e1*e1);
      float ec = wsum(e0*c0+e1*c1);
      float k  = (ee > 1e-8f) ? ec/fmaxf(ee,1e-8f) : 0.f;
      float f0 = c0 - k*e0, f1 = c1 - k*e1;
      g_Ceff[row*ND+lane]    = f0;
      g_Ceff[row*ND+32+lane] = f1;
      float fb = wsum(formb[lane]*f0 + formb[lane+32]*f1);
      if (!lane) g_FbC[row] = fb;
    }
  }
}

// =============== P2S: stage-2 folds (warp dots) ===============
// blocks 0..255: M4 rows. block 256: biases.
__global__ __launch_bounds__(256) void p2s_kernel(
  const float* __restrict__ canch, const float* __restrict__ acanch)
{
  const int b_ = blockIdx.x, t = threadIdx.x, w = t>>5, lane = t&31;
  const float* Zq = g_M5;
  const float* Lk = g_M5 + 1*ND*NDM;
  const float* Lv = g_M5 + 2*ND*NDM;
  const float* Ck = g_M5 + 3*ND*NDM;
  const float* Cv = g_M5 + 4*ND*NDM;

  if (b_ < 256){
    int y = b_>>6, i = b_&63;
    float* Orow = g_M4 + (y*ND + i)*NC;
    if (y==0){
      const float* A0 = Zq + i*NDM;
      if (t < 48) Orow[48+t] = (t<16)? acanch[t*ND+i] : canch[(t-16)*ND+i];
      for (int jj=w; jj<50; jj+=8){
        const float* B = (jj<16)? g_AKC+jj*NDM : (jj<48)? g_KC+(jj-16)*NDM
                       : (jj==48)? g_B6+NDM : g_B6+3*NDM;
        float s = dot256(A0, B, lane);
        if (!lane) Orow[(jj<48)? jj : 48+jj] = s;   // 48->96, 49->97
      }
    } else if (y<=2){
      const float* Ki = ((y==1)? Lk : Ck) + i*NDM;
      const float* Vi = ((y==1)? Lv : Cv) + i*NDM;
      for (int jj=w; jj<129; jj+=8){
        const float* A; const float* B;
        if (jj<64)       { A=Ki; B=Zq + jj*NDM; }
        else if (jj<128) { A=Vi; B=g_M2T2 + (jj-64)*NDM; }
        else             { A=Ki; B=g_B6; }
        float s = dot256(A, B, lane);
        if (!lane) Orow[jj] = s;
      }
    } else {
      const float* A0 = g_M2T2 + i*NDM;
      for (int jj=w; jj<50; jj+=8){
        const float* B = (jj<16)? g_AVC+jj*NDM : (jj<48)? g_VC+(jj-16)*NDM
                       : (jj==48)? g_B6+2*NDM : g_B6+4*NDM;
        float s = dot256(A0, B, lane);
        if (!lane) Orow[jj] = s;
      }
    }
    return;
  }
  // b_ == 256: biases
  for (int idx=t; idx<4*NC; idx+=256) g_bz[idx] = 0.f;
  __syncthreads();
  for (int jj=w; jj<50; jj+=8){
    const float* B = (jj<16)? g_AKC+jj*NDM : (jj<48)? g_KC+(jj-16)*NDM
                   : (jj==48)? g_B6+NDM : g_B6+3*NDM;
    float s = dot256(g_B6, B, lane);
    if (!lane) g_bz[(jj<48)? jj : 48+jj] = s;
  }
}

// =============== G2: four [4096,64]@[64,cols] GEMMs ===============
__global__ __launch_bounds__(256) void g2_kernel(
  const float* __restrict__ z, const float* __restrict__ az, const float* __restrict__ acz)
{
  __shared__ __align__(16) float xsT[64*68];
  const int t = threadIdx.x, y = blockIdx.y, b0 = blockIdx.x*64;
  const int colsY = (y==0)? 98 : (y==3)? 50 : 129;
  const float* X = (y==0)? z : (y==1)? az : (y==2)? acz : g_Ceff;
  const float* M = g_M4 + y*ND*NC;
  for (int idx=t; idx<4096; idx+=256){
    int bb = idx>>6, ii = idx&63;
    xsT[ii*68+bb] = X[(b0+bb)*ND+ii];
  }
  __syncthreads();
  if (t >= colsY) return;
  float acc[64];
  #pragma unroll
  for (int i=0;i<64;i++) acc[i]=0.f;
  #pragma unroll 1
  for (int i=0;i<ND;i++){
    float mv = M[i*NC+t];
    const float4* x4 = reinterpret_cast<const float4*>(xsT + i*68);
    #pragma unroll
    for (int b4=0;b4<16;b4++){
      float4 xv = x4[b4];
      acc[4*b4+0]+=xv.x*mv; acc[4*b4+1]+=xv.y*mv;
      acc[4*b4+2]+=xv.z*mv; acc[4*b4+3]+=xv.w*mv;
    }
  }
  float bj = g_bz[y*NC+t];
  float* op = g_Gout + ((size_t)y*NB + b0)*NC + t;
  #pragma unroll 1
  for (int bb=0;bb<64;bb++) op[(size_t)bb*NC] = acc[bb] + bj;
}

// =============== F: attention (blocks 0..511) + sigma (block 512) ===============
__global__ __launch_bounds__(256) void f_kernel(
  const float* __restrict__ z,  const float* __restrict__ rw,
  const float* __restrict__ az, const float* __restrict__ arw,
  const float* __restrict__ acz, float* __restrict__ out)
{
  __shared__ __align__(16) float sA[4096];
  __shared__ __align__(16) float sB[4096];
  __shared__ float sv[64];
  const int t = threadIdx.x;

  if (blockIdx.x == 512){
    // ---- sigma: 3 register-tiled squarings (G^8) + 20 power iters + Rayleigh ----
    #pragma unroll
    for (int r=0;r<16;r++) sA[t+r*256] = g_G[t+r*256];
    __syncthreads();
    const int pr = (t>>4)*4, pc = (t&15)*4;
    for (int sq=0; sq<3; sq++){
      float4 ac0=make_float4(0,0,0,0), ac1=ac0, ac2=ac0, ac3=ac0;
      #pragma unroll 4
      for (int q=0;q<64;q++){
        float4 bv = *(const float4*)(sA + q*64 + pc);
        float a0=sA[(pr+0)*64+q], a1=sA[(pr+1)*64+q], a2=sA[(pr+2)*64+q], a3=sA[(pr+3)*64+q];
        ac0.x+=a0*bv.x; ac0.y+=a0*bv.y; ac0.z+=a0*bv.z; ac0.w+=a0*bv.w;
        ac1.x+=a1*bv.x; ac1.y+=a1*bv.y; ac1.z+=a1*bv.z; ac1.w+=a1*bv.w;
        ac2.x+=a2*bv.x; ac2.y+=a2*bv.y; ac2.z+=a2*bv.z; ac2.w+=a2*bv.w;
        ac3.x+=a3*bv.x; ac3.y+=a3*bv.y; ac3.z+=a3*bv.z; ac3.w+=a3*bv.w;
      }
      *(float4*)(sB+(pr+0)*64+pc)=ac0; *(float4*)(sB+(pr+1)*64+pc)=ac1;
      *(float4*)(sB+(pr+2)*64+pc)=ac2; *(float4*)(sB+(pr+3)*64+pc)=ac3;
      __syncthreads();
      #pragma unroll
      for (int k=0;k<4;k++) ((float4*)sA)[t*4+k] = ((const float4*)sB)[t*4+k];
      __syncthreads();
    }
    if (t < 32){
      int lane=t;
      sv[lane]=1.f; sv[lane+32]=1.f; __syncwarp();
      for (int it=0; it<20; it++){
        float y0=0.f, y1=0.f;
        for (int q=0;q<64;q++){ float vq=sv[q]; y0+=sA[q*64+lane]*vq; y1+=sA[q*64+32+lane]*vq; }
        float rn = rsqrtf(wsum(y0*y0+y1*y1));
        sv[lane]=y0*rn; sv[lane+32]=y1*rn; __syncwarp();
      }
      float p0=0.f, p1=0.f;
      for (int q=0;q<64;q++){ float vq=sv[q]; p0+=g_G[lane*64+q]*vq; p1+=g_G[(lane+32)*64+q]*vq; }
      float lam = wsum(p0*sv[lane]+p1*sv[lane+32]);
      if (!lane) g_inv_sigma = 1.f/fmaxf(sqrtf(fmaxf(lam,0.f)),1e-8f);
    }
    return;
  }

  const int w = t>>5, lane = t&31;
  const int b = blockIdx.x*8 + w;

  const float* gz   = g_Gout + (size_t)b*NC;
  const float* gaz  = g_Gout + ((size_t)NB + b)*NC;
  const float* gacz = g_Gout + ((size_t)2*NB + b)*NC;
  const float* gc   = g_Gout + ((size_t)3*NB + b)*NC;

  float z0  = z[b*ND+lane],   z1  = z[b*ND+32+lane];
  float a0  = az[b*ND+lane],  a1  = az[b*ND+32+lane];
  float c0  = acz[b*ND+lane], c1  = acz[b*ND+32+lane];
  float ce0 = g_Ceff[b*ND+lane], ce1 = g_Ceff[b*ND+32+lane];

  float d_z2   = wsum(z0*z0 + z1*z1);
  float d_zaz  = wsum(z0*a0 + z1*a1);
  float d_az2  = wsum(a0*a0 + a1*a1);
  float d_zacz = wsum(z0*c0 + z1*c1);
  float d_acz2 = wsum(c0*c0 + c1*c1);
  float y1a = gaz[lane],  y1b = gaz[32+lane];
  float d_zy1  = wsum(z0*y1a + z1*y1b);
  float y2a = gacz[lane], y2b = gacz[32+lane];
  float d_zy2  = wsum(z0*y2a + z1*y2b);
  float y3a = gaz[64+lane],  y3b = gaz[96+lane];
  float d_cy3  = wsum(ce0*y3a + ce1*y3b);
  float y4a = gacz[64+lane], y4b = gacz[96+lane];
  float d_cy4  = wsum(ce0*y4a + ce1*y4b);

  float s0, t0, s1 = -1e30f, t1 = 0.f;
  {
    int tok = lane;
    if (tok == 0){
      s0 = (d_zy1 + gz[96] + gaz[128])*0.0625f - (d_z2 - 2.f*d_zaz + d_az2);
      t0 = d_cy3 + gc[48];
    } else if (tok == 1){
      s0 = (d_zy2 + gz[97] + gacz[128])*0.0625f - (d_z2 - 2.f*d_zacz + d_acz2);
      t0 = d_cy4 + gc[49];
    } else if (tok < 18){
      int k = tok-2; float aw = arw[b*NKA+k];
      s0 = aw*gz[k]*0.0625f - (d_z2 - 2.f*gz[48+k] + g_aan2[k]);
      t0 = aw*gc[k];
    } else {
      int k = tok-18; float cw = rw[b*NK+k];
      s0 = cw*gz[16+k]*0.0625f - (d_z2 - 2.f*gz[64+k] + g_an2[k]);
      t0 = cw*gc[16+k];
    }
  }
  if (lane < 18){
    int k = lane + 14;
    float cw = rw[b*NK+k];
    s1 = cw*gz[16+k]*0.0625f - (d_z2 - 2.f*gz[64+k] + g_an2[k]);
    t1 = cw*gc[16+k];
  }

  float m = wmax(fmaxf(s0, s1));
  float e0 = __expf(s0 - m);
  float e1 = (lane < 18) ? __expf(s1 - m) : 0.f;
  float den = wsum(e0 + e1);
  float num = wsum(e0*t0 + e1*t1);
  if (!lane) out[b] = num / den;       // raw; scaled by scale_kernel
}

// =============== SCALE: out = inv_sigma*raw + FbC ===============
__global__ __launch_bounds__(256) void scale_kernel(float* __restrict__ out){
  int i = blockIdx.x*256 + threadIdx.x;
  out[i] = g_inv_sigma*out[i] + g_FbC[i];
}

// =============== launch ===============
extern "C" void kernel_launch(void* const* d_in, const int* in_sizes, int n_in,
                              void* d_out, int out_size)
{
  const float* z     =(const float*)d_in[0];
  const float* rw    =(const float*)d_in[1];
  const float* az    =(const float*)d_in[2];
  const float* arw   =(const float*)d_in[3];
  const float* acz   =(const float*)d_in[4];
  const float* ctrl  =(const float*)d_in[5];
  const float* ecov  =(const float*)d_in[6];
  const float* cemb  =(const float*)d_in[7];
  const float* canch =(const float*)d_in[8];
  const float* acemb =(const float*)d_in[9];
  const float* acanch=(const float*)d_in[10];
  const float* zW    =(const float*)d_in[11];
  const float* zb    =(const float*)d_in[12];
  const float* latW  =(const float*)d_in[13];
  const float* latb  =(const float*)d_in[14];
  const float* codeW =(const float*)d_in[15];
  const float* codeb =(const float*)d_in[16];
  const float* Wq    =(const float*)d_in[17];
  const float* Wk    =(const float*)d_in[18];
  const float* Wv    =(const float*)d_in[19];
  const float* Wo    =(const float*)d_in[20];
  const float* formW =(const float*)d_in[21];
  const float* formb =(const float*)d_in[22];
  float* out = (float*)d_out;

  p_kernel<<<206,256>>>(zW,latW,codeW,Wq,Wk,Wv,Wo,cemb,acemb,formW,
                        zb,latb,codeb,canch,acanch,ctrl,ecov,formb);
  p2s_kernel<<<257,256>>>(canch,acanch);
  g2_kernel<<<dim3(64,4),256>>>(z,az,acz);
  f_kernel<<<513,256>>>(z,rw,az,arw,acz,out);
  scale_kernel<<<16,256>>>(out);
}

// round 8
// speedup vs baseline: 2.7167x; 1.6128x over previous
#include <cuda_runtime.h>
#include <cuda_bf16.h>

#define NB  4096
#define ND  64
#define NDM 256
#define NK  32
#define NKA 16
#define NC  160   // M4 row stride (padded); active cols per y: 98,129,129,50

// ----- device scratch (16B aligned for float4) -----
__device__ __align__(16) float g_M5[5*ND*NDM];   // Zq, Lk, Lv, Ck, Cv
__device__ __align__(16) float g_B6[5*NDM];      // bq, bLk, bLv, bCk, bCv
__device__ __align__(16) float g_KC[NK*NDM], g_VC[NK*NDM];
__device__ __align__(16) float g_AKC[NKA*NDM], g_AVC[NKA*NDM];
__device__ float g_an2[NK], g_aan2[NKA];
__device__ __align__(16) float g_M2T2[ND*NDM];   // (Wo@form_W)^T : [d][j]
__device__ __align__(16) float g_G[ND*ND];       // form_W^T form_W
__device__ __align__(16) float g_Ceff[NB*ND];
__device__ float g_FbC[NB];
__device__ float g_inv_sigma;
__device__ __align__(16) float g_M4[4*ND*NC];    // folded GEMM matrices
__device__ __align__(16) float g_bz[4*NC];

__device__ __forceinline__ float wsum(float v){
  #pragma unroll
  for(int o=16;o>0;o>>=1) v += __shfl_xor_sync(0xffffffffu,v,o);
  return v;
}
__device__ __forceinline__ float wmax(float v){
  #pragma unroll
  for(int o=16;o>0;o>>=1) v = fmaxf(v,__shfl_xor_sync(0xffffffffu,v,o));
  return v;
}
// warp dot of two 256-float vectors, both 16B aligned
__device__ __forceinline__ float dot256(const float* __restrict__ A,
                                        const float* __restrict__ B, int lane){
  float4 a0 = *(const float4*)(A + lane*8);
  float4 a1 = *(const float4*)(A + lane*8 + 4);
  float4 b0 = *(const float4*)(B + lane*8);
  float4 b1 = *(const float4*)(B + lane*8 + 4);
  float s = a0.x*b0.x + a0.y*b0.y + a0.z*b0.z + a0.w*b0.w
          + a1.x*b1.x + a1.y*b1.y + a1.z*b1.z + a1.w*b1.w;
  return wsum(s);
}

// =============== P1: stage-1 folds (verbatim R7, known-good) ===============
__global__ __launch_bounds__(256) void p_kernel(
  const float* __restrict__ zW,   const float* __restrict__ latW, const float* __restrict__ codeW,
  const float* __restrict__ Wq,   const float* __restrict__ Wk,   const float* __restrict__ Wv,
  const float* __restrict__ Wo,   const float* __restrict__ cemb, const float* __restrict__ acemb,
  const float* __restrict__ formW,const float* __restrict__ zb,   const float* __restrict__ latb,
  const float* __restrict__ codeb,const float* __restrict__ canch,const float* __restrict__ acanch,
  const float* __restrict__ ctrl, const float* __restrict__ ecov, const float* __restrict__ formb)
{
  int blk = blockIdx.x;
  const int t = threadIdx.x;

  if (blk < 80) {                 // five folded [64,256] matrices A@W
    int m = blk>>4;
    int r = (blk&15)*4 + (t>>6);
    int c4 = (t&63)*4;
    const float* A  = (m==0)? zW : (m<3 ? latW : codeW);
    const float* Bm = (m==0)? Wq : ((m==1||m==3)? Wk : Wv);
    const float* Ar = A + r*NDM;
    float4 acc = make_float4(0.f,0.f,0.f,0.f);
    #pragma unroll 8
    for (int i=0;i<NDM;i++){
      float a = Ar[i];
      float4 bv = *(const float4*)(Bm + i*NDM + c4);
      acc.x += a*bv.x; acc.y += a*bv.y; acc.z += a*bv.z; acc.w += a*bv.w;
    }
    *(float4*)(g_M5 + m*(ND*NDM) + r*NDM + c4) = acc;
    return;
  }
  blk -= 80;
  if (blk < 24) {                 // chart tables
    int g = blk*4 + (t>>6);
    int c4 = (t&63)*4;
    const float* Ar; const float* Bm; float* O; int lr;
    if (g < 32)      { Ar=cemb  + g*NDM;      Bm=Wk; O=g_KC;  lr=g;    }
    else if (g < 64) { Ar=cemb  + (g-32)*NDM; Bm=Wv; O=g_VC;  lr=g-32; }
    else if (g < 80) { Ar=acemb + (g-64)*NDM; Bm=Wk; O=g_AKC; lr=g-64; }
    else             { Ar=acemb + (g-80)*NDM; Bm=Wv; O=g_AVC; lr=g-80; }
    float4 acc = make_float4(0.f,0.f,0.f,0.f);
    #pragma unroll 8
    for (int i=0;i<NDM;i++){
      float a = Ar[i];
      float4 bv = *(const float4*)(Bm + i*NDM + c4);
      acc.x += a*bv.x; acc.y += a*bv.y; acc.z += a*bv.z; acc.w += a*bv.w;
    }
    *(float4*)(O + lr*NDM + c4) = acc;
    return;
  }
  blk -= 24;
  if (blk < 16) {                 // M2T2[d][j] = sum_i Wo[j][i]*formW[i][d]
    int j = blk*16 + (t>>4);
    int d4 = (t&15)*4;
    float4 acc = make_float4(0.f,0.f,0.f,0.f);
    #pragma unroll 8
    for (int i=0;i<NDM;i++){
      float wv = Wo[j*NDM+i];
      float4 fv = *(const float4*)(formW + i*ND + d4);
      acc.x += wv*fv.x; acc.y += wv*fv.y; acc.z += wv*fv.z; acc.w += wv*fv.w;
    }
    g_M2T2[(d4+0)*NDM+j]=acc.x; g_M2T2[(d4+1)*NDM+j]=acc.y;
    g_M2T2[(d4+2)*NDM+j]=acc.z; g_M2T2[(d4+3)*NDM+j]=acc.w;
    return;
  }
  blk -= 16;
  if (blk < 16) {                 // G = formW^T formW
    int idx = blk*256 + t, p = idx>>6, q = idx&63;
    float s = 0.f;
    #pragma unroll 8
    for (int i=0;i<NDM;i++) s += formW[i*ND+p]*formW[i*ND+q];
    g_G[idx] = s;
    return;
  }
  blk -= 16;
  if (blk < 5) {                  // folded bias vectors
    const float* vv = (blk==0)? zb : (blk<3 ? latb : codeb);
    const float* Bm = (blk==0)? Wq : ((blk==1||blk==3)? Wk : Wv);
    float s = 0.f;
    #pragma unroll 8
    for (int i=0;i<NDM;i++) s += vv[i]*Bm[i*NDM+t];
    g_B6[blk*NDM+t] = s;
    return;
  }
  blk -= 5;
  if (blk < 1) {                  // anchor norms
    if (t < 32) {
      float s=0.f;
      for (int i=0;i<ND;i++){ float v=canch[t*ND+i]; s+=v*v; }
      g_an2[t]=s;
    } else if (t < 48) {
      int k=t-32; float s=0.f;
      for (int i=0;i<ND;i++){ float v=acanch[k*ND+i]; s+=v*v; }
      g_aan2[k]=s;
    }
    return;
  }
  blk -= 1;
  {                               // 64 blocks: ceff + form_b.ceff
    int w = t>>5, lane = t&31;
    #pragma unroll 1
    for (int rr=0; rr<8; rr++){
      int row = blk*64 + w*8 + rr;
      float e0=ecov[row*ND+lane], e1=ecov[row*ND+32+lane];
      float c0=ctrl[row*ND+lane], c1=ctrl[row*ND+32+lane];
      float ee = wsum(e0*e0+e1*e1);
      float ec = wsum(e0*c0+e1*c1);
      float k  = (ee > 1e-8f) ? ec/fmaxf(ee,1e-8f) : 0.f;
      float f0 = c0 - k*e0, f1 = c1 - k*e1;
      g_Ceff[row*ND+lane]    = f0;
      g_Ceff[row*ND+32+lane] = f1;
      float fb = wsum(formb[lane]*f0 + formb[lane+32]*f1);
      if (!lane) g_FbC[row] = fb;
    }
  }
}

// =============== P2S: stage-2 folds + sigma (block 257) ===============
__global__ __launch_bounds__(256) void p2s_kernel(
  const float* __restrict__ canch, const float* __restrict__ acanch)
{
  __shared__ __align__(16) float sA[4096];
  __shared__ __align__(16) float sB[4096];
  __shared__ float sv[64];
  const int b_ = blockIdx.x, t = threadIdx.x, w = t>>5, lane = t&31;
  const float* Zq = g_M5;
  const float* Lk = g_M5 + 1*ND*NDM;
  const float* Lv = g_M5 + 2*ND*NDM;
  const float* Ck = g_M5 + 3*ND*NDM;
  const float* Cv = g_M5 + 4*ND*NDM;

  if (b_ < 256){
    int y = b_>>6, i = b_&63;
    float* Orow = g_M4 + (y*ND + i)*NC;
    if (y==0){
      const float* A0 = Zq + i*NDM;
      if (t < 48) Orow[48+t] = (t<16)? acanch[t*ND+i] : canch[(t-16)*ND+i];
      for (int jj=w; jj<50; jj+=8){
        const float* B = (jj<16)? g_AKC+jj*NDM : (jj<48)? g_KC+(jj-16)*NDM
                       : (jj==48)? g_B6+NDM : g_B6+3*NDM;
        float s = dot256(A0, B, lane);
        if (!lane) Orow[(jj<48)? jj : 48+jj] = s;   // 48->96, 49->97
      }
    } else if (y<=2){
      const float* Ki = ((y==1)? Lk : Ck) + i*NDM;
      const float* Vi = ((y==1)? Lv : Cv) + i*NDM;
      for (int jj=w; jj<129; jj+=8){
        const float* A; const float* B;
        if (jj<64)       { A=Ki; B=Zq + jj*NDM; }
        else if (jj<128) { A=Vi; B=g_M2T2 + (jj-64)*NDM; }
        else             { A=Ki; B=g_B6; }
        float s = dot256(A, B, lane);
        if (!lane) Orow[jj] = s;
      }
    } else {
      const float* A0 = g_M2T2 + i*NDM;
      for (int jj=w; jj<50; jj+=8){
        const float* B = (jj<16)? g_AVC+jj*NDM : (jj<48)? g_VC+(jj-16)*NDM
                       : (jj==48)? g_B6+2*NDM : g_B6+4*NDM;
        float s = dot256(A0, B, lane);
        if (!lane) Orow[jj] = s;
      }
    }
    return;
  }
  if (b_ == 256){                 // biases
    for (int idx=t; idx<4*NC; idx+=256) g_bz[idx] = 0.f;
    __syncthreads();
    for (int jj=w; jj<50; jj+=8){
      const float* B = (jj<16)? g_AKC+jj*NDM : (jj<48)? g_KC+(jj-16)*NDM
                     : (jj==48)? g_B6+NDM : g_B6+3*NDM;
      float s = dot256(g_B6, B, lane);
      if (!lane) g_bz[(jj<48)? jj : 48+jj] = s;
    }
    return;
  }
  // ---- block 257: sigma = 3 register-tiled squarings (G^8) + 16 power iters + Rayleigh ----
  #pragma unroll
  for (int r=0;r<16;r++) sA[t+r*256] = g_G[t+r*256];
  __syncthreads();
  const int pr = (t>>4)*4, pc = (t&15)*4;
  for (int sq=0; sq<3; sq++){
    float4 ac0=make_float4(0,0,0,0), ac1=ac0, ac2=ac0, ac3=ac0;
    #pragma unroll 4
    for (int q=0;q<64;q++){
      float4 bv = *(const float4*)(sA + q*64 + pc);
      float a0=sA[(pr+0)*64+q], a1=sA[(pr+1)*64+q], a2=sA[(pr+2)*64+q], a3=sA[(pr+3)*64+q];
      ac0.x+=a0*bv.x; ac0.y+=a0*bv.y; ac0.z+=a0*bv.z; ac0.w+=a0*bv.w;
      ac1.x+=a1*bv.x; ac1.y+=a1*bv.y; ac1.z+=a1*bv.z; ac1.w+=a1*bv.w;
      ac2.x+=a2*bv.x; ac2.y+=a2*bv.y; ac2.z+=a2*bv.z; ac2.w+=a2*bv.w;
      ac3.x+=a3*bv.x; ac3.y+=a3*bv.y; ac3.z+=a3*bv.z; ac3.w+=a3*bv.w;
    }
    __syncthreads();
    *(float4*)(sB+(pr+0)*64+pc)=ac0; *(float4*)(sB+(pr+1)*64+pc)=ac1;
    *(float4*)(sB+(pr+2)*64+pc)=ac2; *(float4*)(sB+(pr+3)*64+pc)=ac3;
    __syncthreads();
    #pragma unroll
    for (int k=0;k<4;k++) ((float4*)sA)[t*4+k] = ((const float4*)sB)[t*4+k];
    __syncthreads();
  }
  if (t < 32){
    sv[lane]=1.f; sv[lane+32]=1.f; __syncwarp();
    for (int it=0; it<16; it++){
      float y0=0.f, y1=0.f;
      for (int q=0;q<64;q++){ float vq=sv[q]; y0+=sA[q*64+lane]*vq; y1+=sA[q*64+32+lane]*vq; }
      float rn = rsqrtf(wsum(y0*y0+y1*y1));
      sv[lane]=y0*rn; sv[lane+32]=y1*rn; __syncwarp();
    }
    float p0=0.f, p1=0.f;       // Rayleigh on ORIGINAL G
    for (int q=0;q<64;q++){ float vq=sv[q]; p0+=g_G[lane*64+q]*vq; p1+=g_G[(lane+32)*64+q]*vq; }
    float lam = wsum(p0*sv[lane]+p1*sv[lane+32]);
    if (!lane) g_inv_sigma = 1.f/fmaxf(sqrtf(fmaxf(lam,0.f)),1e-8f);
  }
}

// =============== GF: fused GEMM-tile + attention + epilogue ===============
// 256 blocks x 512 threads, 16 batches/block. smem: xsT 20.5KB + sg 26.6KB = 47.1KB
#define SG_STRIDE 416   // col offsets: y0=0 (98), y1=98 (129), y2=227 (129), y3=356 (50)
__global__ __launch_bounds__(512) void gf_kernel(
  const float* __restrict__ z,  const float* __restrict__ rw,
  const float* __restrict__ az, const float* __restrict__ arw,
  const float* __restrict__ acz, float* __restrict__ out)
{
  __shared__ __align__(16) float xsT[4*64*20];        // [y][i][bb], bb stride 20
  __shared__ float sg[16*SG_STRIDE];                  // [bat][col]
  const int t = threadIdx.x;
  const int b0 = blockIdx.x*16;

  // load X^T tiles: y in {z, az, acz, Ceff}
  for (int idx=t; idx<4096; idx+=512){
    int y = idx>>10, r = idx&1023, bb = r>>6, i = r&63;
    const float* X = (y==0)? z : (y==1)? az : (y==2)? acz : g_Ceff;
    xsT[(y*64+i)*20 + bb] = X[(b0+bb)*ND + i];
  }
  __syncthreads();

  // GEMM phase: thread -> (y, col); output col index == t
  if (t < 406){
    int y, col;
    if (t<98){y=0;col=t;} else if (t<227){y=1;col=t-98;}
    else if (t<356){y=2;col=t-227;} else {y=3;col=t-356;}
    const float* M  = g_M4 + (y*ND)*NC + col;
    const float* xb = xsT + (y*64)*20;
    float a0=0,a1=0,a2=0,a3=0,a4=0,a5=0,a6=0,a7=0,a8=0,a9=0,aa=0,ab=0,ac=0,ad=0,ae=0,af=0;
    #pragma unroll 4
    for (int i=0;i<64;i++){
      float mv = M[(size_t)i*NC];
      const float4* x4 = (const float4*)(xb + i*20);
      float4 v0=x4[0], v1=x4[1], v2=x4[2], v3=x4[3];
      a0+=mv*v0.x; a1+=mv*v0.y; a2+=mv*v0.z; a3+=mv*v0.w;
      a4+=mv*v1.x; a5+=mv*v1.y; a6+=mv*v1.z; a7+=mv*v1.w;
      a8+=mv*v2.x; a9+=mv*v2.y; aa+=mv*v2.z; ab+=mv*v2.w;
      ac+=mv*v3.x; ad+=mv*v3.y; ae+=mv*v3.z; af+=mv*v3.w;
    }
    float bz = g_bz[y*NC+col];
    sg[ 0*SG_STRIDE+t]=a0+bz; sg[ 1*SG_STRIDE+t]=a1+bz;
    sg[ 2*SG_STRIDE+t]=a2+bz; sg[ 3*SG_STRIDE+t]=a3+bz;
    sg[ 4*SG_STRIDE+t]=a4+bz; sg[ 5*SG_STRIDE+t]=a5+bz;
    sg[ 6*SG_STRIDE+t]=a6+bz; sg[ 7*SG_STRIDE+t]=a7+bz;
    sg[ 8*SG_STRIDE+t]=a8+bz; sg[ 9*SG_STRIDE+t]=a9+bz;
    sg[10*SG_STRIDE+t]=aa+bz; sg[11*SG_STRIDE+t]=ab+bz;
    sg[12*SG_STRIDE+t]=ac+bz; sg[13*SG_STRIDE+t]=ad+bz;
    sg[14*SG_STRIDE+t]=ae+bz; sg[15*SG_STRIDE+t]=af+bz;
  }
  __syncthreads();

  // attention phase: warp w -> batch b0+w
  const int w = t>>5, lane = t&31;
  const int b = b0 + w;
  const float* gz   = sg + w*SG_STRIDE;
  const float* gaz  = gz + 98;
  const float* gacz = gz + 227;
  const float* gc   = gz + 356;

  float z0  = z[b*ND+lane],   z1  = z[b*ND+32+lane];
  float a0  = az[b*ND+lane],  a1  = az[b*ND+32+lane];
  float c0  = acz[b*ND+lane], c1  = acz[b*ND+32+lane];
  float ce0 = g_Ceff[b*ND+lane], ce1 = g_Ceff[b*ND+32+lane];

  float d_z2   = wsum(z0*z0 + z1*z1);
  float d_zaz  = wsum(z0*a0 + z1*a1);
  float d_az2  = wsum(a0*a0 + a1*a1);
  float d_zacz = wsum(z0*c0 + z1*c1);
  float d_acz2 = wsum(c0*c0 + c1*c1);
  float d_zy1  = wsum(z0*gaz[lane]     + z1*gaz[32+lane]);
  float d_zy2  = wsum(z0*gacz[lane]    + z1*gacz[32+lane]);
  float d_cy3  = wsum(ce0*gaz[64+lane] + ce1*gaz[96+lane]);
  float d_cy4  = wsum(ce0*gacz[64+lane]+ ce1*gacz[96+lane]);

  float s0, t0, s1 = -1e30f, t1 = 0.f;
  {
    int tok = lane;
    if (tok == 0){
      s0 = (d_zy1 + gz[96] + gaz[128])*0.0625f - (d_z2 - 2.f*d_zaz + d_az2);
      t0 = d_cy3 + gc[48];
    } else if (tok == 1){
      s0 = (d_zy2 + gz[97] + gacz[128])*0.0625f - (d_z2 - 2.f*d_zacz + d_acz2);
      t0 = d_cy4 + gc[49];
    } else if (tok < 18){
      int k = tok-2; float aw = arw[b*NKA+k];
      s0 = aw*gz[k]*0.0625f - (d_z2 - 2.f*gz[48+k] + g_aan2[k]);
      t0 = aw*gc[k];
    } else {
      int k = tok-18; float cw = rw[b*NK+k];
      s0 = cw*gz[16+k]*0.0625f - (d_z2 - 2.f*gz[64+k] + g_an2[k]);
      t0 = cw*gc[16+k];
    }
  }
  if (lane < 18){
    int k = lane + 14;     // token lane+32 = chart k = lane+14
    float cw = rw[b*NK+k];
    s1 = cw*gz[16+k]*0.0625f - (d_z2 - 2.f*gz[64+k] + g_an2[k]);
    t1 = cw*gc[16+k];
  }

  float m = wmax(fmaxf(s0, s1));
  float e0 = __expf(s0 - m);
  float e1 = (lane < 18) ? __expf(s1 - m) : 0.f;
  float den = wsum(e0 + e1);
  float num = wsum(e0*t0 + e1*t1);
  if (!lane) out[b] = g_inv_sigma * num / den + g_FbC[b];
}

// =============== launch ===============
extern "C" void kernel_launch(void* const* d_in, const int* in_sizes, int n_in,
                              void* d_out, int out_size)
{
  const float* z     =(const float*)d_in[0];
  const float* rw    =(const float*)d_in[1];
  const float* az    =(const float*)d_in[2];
  const float* arw   =(const float*)d_in[3];
  const float* acz   =(const float*)d_in[4];
  const float* ctrl  =(const float*)d_in[5];
  const float* ecov  =(const float*)d_in[6];
  const float* cemb  =(const float*)d_in[7];
  const float* canch =(const float*)d_in[8];
  const float* acemb =(const float*)d_in[9];
  const float* acanch=(const float*)d_in[10];
  const float* zW    =(const float*)d_in[11];
  const float* zb    =(const float*)d_in[12];
  const float* latW  =(const float*)d_in[13];
  const float* latb  =(const float*)d_in[14];
  const float* codeW =(const float*)d_in[15];
  const float* codeb =(const float*)d_in[16];
  const float* Wq    =(const float*)d_in[17];
  const float* Wk    =(const float*)d_in[18];
  const float* Wv    =(const float*)d_in[19];
  const float* Wo    =(const float*)d_in[20];
  const float* formW =(const float*)d_in[21];
  const float* formb =(const float*)d_in[22];
  float* out = (float*)d_out;

  p_kernel<<<206,256>>>(zW,latW,codeW,Wq,Wk,Wv,Wo,cemb,acemb,formW,
                        zb,latb,codeb,canch,acanch,ctrl,ecov,formb);
  p2s_kernel<<<258,256>>>(canch,acanch);
  gf_kernel<<<256,512>>>(z,rw,az,arw,acz,out);
}

// round 9
// speedup vs baseline: 3.2885x; 1.2105x over previous
#include <cuda_runtime.h>
#include <cuda_bf16.h>

#define NB  4096
#define ND  64
#define NDM 256
#define NK  32
#define NKA 16
#define NC  160   // M4 row stride (padded); active cols per y: 98,129,129,50

// ----- device scratch (16B aligned for float4) -----
__device__ __align__(16) float g_M5[5*ND*NDM];   // Zq, Lk, Lv, Ck, Cv
__device__ __align__(16) float g_B6[5*NDM];      // bq, bLk, bLv, bCk, bCv
__device__ __align__(16) float g_KC[NK*NDM], g_VC[NK*NDM];
__device__ __align__(16) float g_AKC[NKA*NDM], g_AVC[NKA*NDM];
__device__ float g_an2[NK], g_aan2[NKA];
__device__ __align__(16) float g_M2T2[ND*NDM];   // (Wo@form_W)^T : [d][j]
__device__ __align__(16) float g_G[ND*ND];       // form_W^T form_W
__device__ __align__(16) float g_Ceff[NB*ND];
__device__ float g_FbC[NB];
__device__ float g_inv_sigma;
__device__ __align__(16) float g_M4[4*ND*NC];    // folded GEMM matrices
__device__ __align__(16) float g_bz[4*NC];

__device__ __forceinline__ float wsum(float v){
  #pragma unroll
  for(int o=16;o>0;o>>=1) v += __shfl_xor_sync(0xffffffffu,v,o);
  return v;
}
__device__ __forceinline__ float wmax(float v){
  #pragma unroll
  for(int o=16;o>0;o>>=1) v = fmaxf(v,__shfl_xor_sync(0xffffffffu,v,o));
  return v;
}
// warp dot of two 256-float vectors, both 16B aligned
__device__ __forceinline__ float dot256(const float* __restrict__ A,
                                        const float* __restrict__ B, int lane){
  float4 a0 = *(const float4*)(A + lane*8);
  float4 a1 = *(const float4*)(A + lane*8 + 4);
  float4 b0 = *(const float4*)(B + lane*8);
  float4 b1 = *(const float4*)(B + lane*8 + 4);
  float s = a0.x*b0.x + a0.y*b0.y + a0.z*b0.z + a0.w*b0.w
          + a1.x*b1.x + a1.y*b1.y + a1.z*b1.z + a1.w*b1.w;
  return wsum(s);
}

// =============== P1: stage-1 folds — tiled GEMM version ===============
// blocks [0,132): 32x32 GEMM tiles:
//   id<112: g=id>>4 (g0 zW@Wq, g1 latW@Wk, g2 codeW@Wk, g3 latW@Wv, g4 codeW@Wv,
//           g5 charts@Wk, g6 charts@Wv), m0=((id&15)>>3)*32, n0=(id&7)*32
//   112..127: g7 Wo@formW (8 Mtiles x 2 Ntiles)
//   128..131: g8 formW^T@formW (2x2)
// then: [132,137) biases | 137 anchors | [138,202) ceff
__global__ __launch_bounds__(256) void p_kernel(
  const float* __restrict__ zW,   const float* __restrict__ latW, const float* __restrict__ codeW,
  const float* __restrict__ Wq,   const float* __restrict__ Wk,   const float* __restrict__ Wv,
  const float* __restrict__ Wo,   const float* __restrict__ cemb, const float* __restrict__ acemb,
  const float* __restrict__ formW,const float* __restrict__ zb,   const float* __restrict__ latb,
  const float* __restrict__ codeb,const float* __restrict__ canch,const float* __restrict__ acanch,
  const float* __restrict__ ctrl, const float* __restrict__ ecov, const float* __restrict__ formb)
{
  __shared__ __align__(16) float As[32*65];   // [r][kk], row pad 65 -> conflict-free
  __shared__ __align__(16) float Bs[64*36];   // [kk][c], row pad 36 (float4-aligned)
  int blk = blockIdx.x;
  const int t = threadIdx.x;

  if (blk < 132){
    int g, m0, n0;
    if (blk < 112){ g = blk>>4; int s = blk&15; m0 = (s>>3)*32; n0 = (s&7)*32; }
    else if (blk < 128){ g = 7; int s = blk-112; m0 = (s>>1)*32; n0 = (s&1)*32; }
    else { g = 8; int s = blk-128; m0 = (s>>1)*32; n0 = (s&1)*32; }

    const float* Bm = (g==0)? Wq : (g==1||g==2||g==5)? Wk
                    : (g>=7)? formW : Wv;
    const int ldb = (g>=7)? 64 : 256;

    float acc0=0.f, acc1=0.f, acc2=0.f, acc3=0.f;
    const int rr = t&31, cw = (t>>5)*4;

    for (int k0=0; k0<256; k0+=64){
      __syncthreads();
      // ---- load A chunk into As[r][kk] ----
      if (g==8){
        #pragma unroll
        for (int p=0;p<8;p++){
          int idx = t + p*256; int kk = idx>>5, r2 = idx&31;
          As[r2*65 + kk] = formW[(k0+kk)*64 + m0 + r2];
        }
      } else {
        int r2 = t>>3, kg = (t&7)*8;
        int grow = m0 + r2;
        const float* Ap; bool valid = true;
        if (g==0) Ap = zW + grow*256;
        else if (g==1||g==3) Ap = latW + grow*256;
        else if (g==2||g==4) Ap = codeW + grow*256;
        else if (g==7) Ap = Wo + grow*256;
        else {
          if (grow < 32) Ap = cemb + grow*256;
          else if (grow < 48) Ap = acemb + (grow-32)*256;
          else { Ap = cemb; valid = false; }
        }
        float4 v0 = valid ? *(const float4*)(Ap + k0 + kg)     : make_float4(0,0,0,0);
        float4 v1 = valid ? *(const float4*)(Ap + k0 + kg + 4) : make_float4(0,0,0,0);
        float* a = As + r2*65 + kg;
        a[0]=v0.x; a[1]=v0.y; a[2]=v0.z; a[3]=v0.w;
        a[4]=v1.x; a[5]=v1.y; a[6]=v1.z; a[7]=v1.w;
      }
      // ---- load B chunk into Bs[kk][c] ----
      #pragma unroll
      for (int p=0;p<8;p++){
        int idx = t + p*256; int kk = idx>>5, c = idx&31;
        Bs[kk*36 + c] = Bm[(k0+kk)*ldb + n0 + c];
      }
      __syncthreads();
      // ---- compute ----
      #pragma unroll 8
      for (int kk=0;kk<64;kk++){
        float av = As[rr*65 + kk];
        float4 bv = *(const float4*)(Bs + kk*36 + cw);
        acc0 += av*bv.x; acc1 += av*bv.y; acc2 += av*bv.z; acc3 += av*bv.w;
      }
    }

    int grow = m0 + rr, gcol = n0 + cw;
    if (g<=4){
      const int off[5] = {0,1,3,2,4};   // g -> g_M5 slot (Zq,Lk,Ck,Lv,Cv order fix)
      *(float4*)(g_M5 + off[g]*(ND*NDM) + grow*NDM + gcol) = make_float4(acc0,acc1,acc2,acc3);
    } else if (g==5||g==6){
      if (grow < 48){
        float* C = (grow<32) ? ((g==5)? g_KC : g_VC) + grow*NDM + gcol
                             : ((g==5)? g_AKC : g_AVC) + (grow-32)*NDM + gcol;
        *(float4*)C = make_float4(acc0,acc1,acc2,acc3);
      }
    } else if (g==7){
      g_M2T2[(gcol+0)*NDM + grow] = acc0;
      g_M2T2[(gcol+1)*NDM + grow] = acc1;
      g_M2T2[(gcol+2)*NDM + grow] = acc2;
      g_M2T2[(gcol+3)*NDM + grow] = acc3;
    } else {
      *(float4*)(g_G + grow*ND + gcol) = make_float4(acc0,acc1,acc2,acc3);
    }
    return;
  }
  blk -= 132;
  if (blk < 5) {                  // folded bias vectors
    const float* vv = (blk==0)? zb : (blk<3 ? latb : codeb);
    const float* Bm = (blk==0)? Wq : ((blk==1||blk==3)? Wk : Wv);
    float s = 0.f;
    #pragma unroll 8
    for (int i=0;i<NDM;i++) s += vv[i]*Bm[i*NDM+t];
    g_B6[blk*NDM+t] = s;
    return;
  }
  blk -= 5;
  if (blk < 1) {                  // anchor norms
    if (t < 32) {
      float s=0.f;
      for (int i=0;i<ND;i++){ float v=canch[t*ND+i]; s+=v*v; }
      g_an2[t]=s;
    } else if (t < 48) {
      int k=t-32; float s=0.f;
      for (int i=0;i<ND;i++){ float v=acanch[k*ND+i]; s+=v*v; }
      g_aan2[k]=s;
    }
    return;
  }
  blk -= 1;
  {                               // 64 blocks: ceff + form_b.ceff
    int w = t>>5, lane = t&31;
    #pragma unroll 1
    for (int rr=0; rr<8; rr++){
      int row = blk*64 + w*8 + rr;
      float e0=ecov[row*ND+lane], e1=ecov[row*ND+32+lane];
      float c0=ctrl[row*ND+lane], c1=ctrl[row*ND+32+lane];
      float ee = wsum(e0*e0+e1*e1);
      float ec = wsum(e0*c0+e1*c1);
      float k  = (ee > 1e-8f) ? ec/fmaxf(ee,1e-8f) : 0.f;
      float f0 = c0 - k*e0, f1 = c1 - k*e1;
      g_Ceff[row*ND+lane]    = f0;
      g_Ceff[row*ND+32+lane] = f1;
      float fb = wsum(formb[lane]*f0 + formb[lane+32]*f1);
      if (!lane) g_FbC[row] = fb;
    }
  }
}

// =============== P2S: stage-2 folds + sigma (block 257) ===============
__global__ __launch_bounds__(256) void p2s_kernel(
  const float* __restrict__ canch, const float* __restrict__ acanch)
{
  __shared__ __align__(16) float sA[4096];
  __shared__ __align__(16) float sB[4096];
  __shared__ float sv[64];
  const int b_ = blockIdx.x, t = threadIdx.x, w = t>>5, lane = t&31;
  const float* Zq = g_M5;
  const float* Lk = g_M5 + 1*ND*NDM;
  const float* Lv = g_M5 + 2*ND*NDM;
  const float* Ck = g_M5 + 3*ND*NDM;
  const float* Cv = g_M5 + 4*ND*NDM;

  if (b_ < 256){
    int y = b_>>6, i = b_&63;
    float* Orow = g_M4 + (y*ND + i)*NC;
    if (y==0){
      const float* A0 = Zq + i*NDM;
      if (t < 48) Orow[48+t] = (t<16)? acanch[t*ND+i] : canch[(t-16)*ND+i];
      for (int jj=w; jj<50; jj+=8){
        const float* B = (jj<16)? g_AKC+jj*NDM : (jj<48)? g_KC+(jj-16)*NDM
                       : (jj==48)? g_B6+NDM : g_B6+3*NDM;
        float s = dot256(A0, B, lane);
        if (!lane) Orow[(jj<48)? jj : 48+jj] = s;   // 48->96, 49->97
      }
    } else if (y<=2){
      const float* Ki = ((y==1)? Lk : Ck) + i*NDM;
      const float* Vi = ((y==1)? Lv : Cv) + i*NDM;
      for (int jj=w; jj<129; jj+=8){
        const float* A; const float* B;
        if (jj<64)       { A=Ki; B=Zq + jj*NDM; }
        else if (jj<128) { A=Vi; B=g_M2T2 + (jj-64)*NDM; }
        else             { A=Ki; B=g_B6; }
        float s = dot256(A, B, lane);
        if (!lane) Orow[jj] = s;
      }
    } else {
      const float* A0 = g_M2T2 + i*NDM;
      for (int jj=w; jj<50; jj+=8){
        const float* B = (jj<16)? g_AVC+jj*NDM : (jj<48)? g_VC+(jj-16)*NDM
                       : (jj==48)? g_B6+2*NDM : g_B6+4*NDM;
        float s = dot256(A0, B, lane);
        if (!lane) Orow[jj] = s;
      }
    }
    return;
  }
  if (b_ == 256){                 // biases
    for (int idx=t; idx<4*NC; idx+=256) g_bz[idx] = 0.f;
    __syncthreads();
    for (int jj=w; jj<50; jj+=8){
      const float* B = (jj<16)? g_AKC+jj*NDM : (jj<48)? g_KC+(jj-16)*NDM
                     : (jj==48)? g_B6+NDM : g_B6+3*NDM;
      float s = dot256(g_B6, B, lane);
      if (!lane) g_bz[(jj<48)? jj : 48+jj] = s;
    }
    return;
  }
  // ---- block 257: sigma = 3 register-tiled squarings (G^8) + 16 power iters + Rayleigh ----
  #pragma unroll
  for (int r=0;r<16;r++) sA[t+r*256] = g_G[t+r*256];
  __syncthreads();
  const int pr = (t>>4)*4, pc = (t&15)*4;
  for (int sq=0; sq<3; sq++){
    float4 ac0=make_float4(0,0,0,0), ac1=ac0, ac2=ac0, ac3=ac0;
    #pragma unroll 4
    for (int q=0;q<64;q++){
      float4 bv = *(const float4*)(sA + q*64 + pc);
      float a0=sA[(pr+0)*64+q], a1=sA[(pr+1)*64+q], a2=sA[(pr+2)*64+q], a3=sA[(pr+3)*64+q];
      ac0.x+=a0*bv.x; ac0.y+=a0*bv.y; ac0.z+=a0*bv.z; ac0.w+=a0*bv.w;
      ac1.x+=a1*bv.x; ac1.y+=a1*bv.y; ac1.z+=a1*bv.z; ac1.w+=a1*bv.w;
      ac2.x+=a2*bv.x; ac2.y+=a2*bv.y; ac2.z+=a2*bv.z; ac2.w+=a2*bv.w;
      ac3.x+=a3*bv.x; ac3.y+=a3*bv.y; ac3.z+=a3*bv.z; ac3.w+=a3*bv.w;
    }
    __syncthreads();
    *(float4*)(sB+(pr+0)*64+pc)=ac0; *(float4*)(sB+(pr+1)*64+pc)=ac1;
    *(float4*)(sB+(pr+2)*64+pc)=ac2; *(float4*)(sB+(pr+3)*64+pc)=ac3;
    __syncthreads();
    #pragma unroll
    for (int k=0;k<4;k++) ((float4*)sA)[t*4+k] = ((const float4*)sB)[t*4+k];
    __syncthreads();
  }
  if (t < 32){
    sv[lane]=1.f; sv[lane+32]=1.f; __syncwarp();
    for (int it=0; it<16; it++){
      float y0=0.f, y1=0.f;
      for (int q=0;q<64;q++){ float vq=sv[q]; y0+=sA[q*64+lane]*vq; y1+=sA[q*64+32+lane]*vq; }
      float rn = rsqrtf(wsum(y0*y0+y1*y1));
      sv[lane]=y0*rn; sv[lane+32]=y1*rn; __syncwarp();
    }
    float p0=0.f, p1=0.f;       // Rayleigh on ORIGINAL G
    for (int q=0;q<64;q++){ float vq=sv[q]; p0+=g_G[lane*64+q]*vq; p1+=g_G[(lane+32)*64+q]*vq; }
    float lam = wsum(p0*sv[lane]+p1*sv[lane+32]);
    if (!lane) g_inv_sigma = 1.f/fmaxf(sqrtf(fmaxf(lam,0.f)),1e-8f);
  }
}

// =============== GF: fused GEMM-tile + attention + epilogue ===============
// 256 blocks x 512 threads, 16 batches/block. smem: xsT 20.5KB + sg 26.6KB = 47.1KB
#define SG_STRIDE 416   // col offsets: y0=0 (98), y1=98 (129), y2=227 (129), y3=356 (50)
__global__ __launch_bounds__(512) void gf_kernel(
  const float* __restrict__ z,  const float* __restrict__ rw,
  const float* __restrict__ az, const float* __restrict__ arw,
  const float* __restrict__ acz, float* __restrict__ out)
{
  __shared__ __align__(16) float xsT[4*64*20];        // [y][i][bb], bb stride 20
  __shared__ float sg[16*SG_STRIDE];                  // [bat][col]
  const int t = threadIdx.x;
  const int b0 = blockIdx.x*16;

  // load X^T tiles: y in {z, az, acz, Ceff}
  for (int idx=t; idx<4096; idx+=512){
    int y = idx>>10, r = idx&1023, bb = r>>6, i = r&63;
    const float* X = (y==0)? z : (y==1)? az : (y==2)? acz : g_Ceff;
    xsT[(y*64+i)*20 + bb] = X[(b0+bb)*ND + i];
  }
  __syncthreads();

  // GEMM phase: thread -> (y, col)
  if (t < 406){
    int y, col;
    if (t<98){y=0;col=t;} else if (t<227){y=1;col=t-98;}
    else if (t<356){y=2;col=t-227;} else {y=3;col=t-356;}
    const float* M  = g_M4 + (y*ND)*NC + col;
    const float* xb = xsT + (y*64)*20;
    float a0=0,a1=0,a2=0,a3=0,a4=0,a5=0,a6=0,a7=0,a8=0,a9=0,aa=0,ab=0,ac=0,ad=0,ae=0,af=0;
    #pragma unroll 4
    for (int i=0;i<64;i++){
      float mv = M[(size_t)i*NC];
      const float4* x4 = (const float4*)(xb + i*20);
      float4 v0=x4[0], v1=x4[1], v2=x4[2], v3=x4[3];
      a0+=mv*v0.x; a1+=mv*v0.y; a2+=mv*v0.z; a3+=mv*v0.w;
      a4+=mv*v1.x; a5+=mv*v1.y; a6+=mv*v1.z; a7+=mv*v1.w;
      a8+=mv*v2.x; a9+=mv*v2.y; aa+=mv*v2.z; ab+=mv*v2.w;
      ac+=mv*v3.x; ad+=mv*v3.y; ae+=mv*v3.z; af+=mv*v3.w;
    }
    float bz = g_bz[y*NC+col];
    sg[ 0*SG_STRIDE+t]=a0+bz; sg[ 1*SG_STRIDE+t]=a1+bz;
    sg[ 2*SG_STRIDE+t]=a2+bz; sg[ 3*SG_STRIDE+t]=a3+bz;
    sg[ 4*SG_STRIDE+t]=a4+bz; sg[ 5*SG_STRIDE+t]=a5+bz;
    sg[ 6*SG_STRIDE+t]=a6+bz; sg[ 7*SG_STRIDE+t]=a7+bz;
    sg[ 8*SG_STRIDE+t]=a8+bz; sg[ 9*SG_STRIDE+t]=a9+bz;
    sg[10*SG_STRIDE+t]=aa+bz; sg[11*SG_STRIDE+t]=ab+bz;
    sg[12*SG_STRIDE+t]=ac+bz; sg[13*SG_STRIDE+t]=ad+bz;
    sg[14*SG_STRIDE+t]=ae+bz; sg[15*SG_STRIDE+t]=af+bz;
  }
  __syncthreads();

  // attention phase: warp w -> batch b0+w
  const int w = t>>5, lane = t&31;
  const int b = b0 + w;
  const float* gz   = sg + w*SG_STRIDE;
  const float* gaz  = gz + 98;
  const float* gacz = gz + 227;
  const float* gc   = gz + 356;

  float z0  = z[b*ND+lane],   z1  = z[b*ND+32+lane];
  float a0  = az[b*ND+lane],  a1  = az[b*ND+32+lane];
  float c0  = acz[b*ND+lane], c1  = acz[b*ND+32+lane];
  float ce0 = g_Ceff[b*ND+lane], ce1 = g_Ceff[b*ND+32+lane];

  float d_z2   = wsum(z0*z0 + z1*z1);
  float d_zaz  = wsum(z0*a0 + z1*a1);
  float d_az2  = wsum(a0*a0 + a1*a1);
  float d_zacz = wsum(z0*c0 + z1*c1);
  float d_acz2 = wsum(c0*c0 + c1*c1);
  float d_zy1  = wsum(z0*gaz[lane]     + z1*gaz[32+lane]);
  float d_zy2  = wsum(z0*gacz[lane]    + z1*gacz[32+lane]);
  float d_cy3  = wsum(ce0*gaz[64+lane] + ce1*gaz[96+lane]);
  float d_cy4  = wsum(ce0*gacz[64+lane]+ ce1*gacz[96+lane]);

  float s0, t0, s1 = -1e30f, t1 = 0.f;
  {
    int tok = lane;
    if (tok == 0){
      s0 = (d_zy1 + gz[96] + gaz[128])*0.0625f - (d_z2 - 2.f*d_zaz + d_az2);
      t0 = d_cy3 + gc[48];
    } else if (tok == 1){
      s0 = (d_zy2 + gz[97] + gacz[128])*0.0625f - (d_z2 - 2.f*d_zacz + d_acz2);
      t0 = d_cy4 + gc[49];
    } else if (tok < 18){
      int k = tok-2; float aw = arw[b*NKA+k];
      s0 = aw*gz[k]*0.0625f - (d_z2 - 2.f*gz[48+k] + g_aan2[k]);
      t0 = aw*gc[k];
    } else {
      int k = tok-18; float cw = rw[b*NK+k];
      s0 = cw*gz[16+k]*0.0625f - (d_z2 - 2.f*gz[64+k] + g_an2[k]);
      t0 = cw*gc[16+k];
    }
  }
  if (lane < 18){
    int k = lane + 14;     // token lane+32 = chart k = lane+14
    float cw = rw[b*NK+k];
    s1 = cw*gz[16+k]*0.0625f - (d_z2 - 2.f*gz[64+k] + g_an2[k]);
    t1 = cw*gc[16+k];
  }

  float m = wmax(fmaxf(s0, s1));
  float e0 = __expf(s0 - m);
  float e1 = (lane < 18) ? __expf(s1 - m) : 0.f;
  float den = wsum(e0 + e1);
  float num = wsum(e0*t0 + e1*t1);
  if (!lane) out[b] = g_inv_sigma * num / den + g_FbC[b];
}

// =============== launch ===============
extern "C" void kernel_launch(void* const* d_in, const int* in_sizes, int n_in,
                              void* d_out, int out_size)
{
  const float* z     =(const float*)d_in[0];
  const float* rw    =(const float*)d_in[1];
  const float* az    =(const float*)d_in[2];
  const float* arw   =(const float*)d_in[3];
  const float* acz   =(const float*)d_in[4];
  const float* ctrl  =(const float*)d_in[5];
  const float* ecov  =(const float*)d_in[6];
  const float* cemb  =(const float*)d_in[7];
  const float* canch =(const float*)d_in[8];
  const float* acemb =(const float*)d_in[9];
  const float* acanch=(const float*)d_in[10];
  const float* zW    =(const float*)d_in[11];
  const float* zb    =(const float*)d_in[12];
  const float* latW  =(const float*)d_in[13];
  const float* latb  =(const float*)d_in[14];
  const float* codeW =(const float*)d_in[15];
  const float* codeb =(const float*)d_in[16];
  const float* Wq    =(const float*)d_in[17];
  const float* Wk    =(const float*)d_in[18];
  const float* Wv    =(const float*)d_in[19];
  const float* Wo    =(const float*)d_in[20];
  const float* formW =(const float*)d_in[21];
  const float* formb =(const float*)d_in[22];
  float* out = (float*)d_out;

  p_kernel<<<202,256>>>(zW,latW,codeW,Wq,Wk,Wv,Wo,cemb,acemb,formW,
                        zb,latb,codeb,canch,acanch,ctrl,ecov,formb);
  p2s_kernel<<<258,256>>>(canch,acanch);
  gf_kernel<<<256,512>>>(z,rw,az,arw,acz,out);
}

// round 10
// speedup vs baseline: 3.5435x; 1.0775x over previous
#include <cuda_runtime.h>
#include <cuda_bf16.h>

#define NB  4096
#define ND  64
#define NDM 256
#define NK  32
#define NKA 16
#define NC  160   // M4 row stride (padded); active cols per y: 98,129,129,50

// ----- device scratch (16B aligned for float4) -----
__device__ __align__(16) float g_M5[5*ND*NDM];   // Zq, Lk, Lv, Ck, Cv
__device__ __align__(16) float g_B6[5*NDM];      // bq, bLk, bLv, bCk, bCv
__device__ __align__(16) float g_KC[NK*NDM], g_VC[NK*NDM];
__device__ __align__(16) float g_AKC[NKA*NDM], g_AVC[NKA*NDM];
__device__ float g_an2[NK], g_aan2[NKA];
__device__ __align__(16) float g_M2T2[ND*NDM];   // (Wo@form_W)^T : [d][j]
__device__ __align__(16) float g_G[ND*ND];       // form_W^T form_W
__device__ __align__(16) float g_Ceff[NB*ND];
__device__ float g_FbC[NB];
__device__ float g_inv_sigma;
__device__ __align__(16) float g_M4[4*ND*NC];    // folded GEMM matrices
__device__ __align__(16) float g_bz[4*NC];

__device__ __forceinline__ float wsum(float v){
  #pragma unroll
  for(int o=16;o>0;o>>=1) v += __shfl_xor_sync(0xffffffffu,v,o);
  return v;
}
__device__ __forceinline__ float wmax(float v){
  #pragma unroll
  for(int o=16;o>0;o>>=1) v = fmaxf(v,__shfl_xor_sync(0xffffffffu,v,o));
  return v;
}
// warp dot of two 256-float vectors, both 16B aligned
__device__ __forceinline__ float dot256(const float* __restrict__ A,
                                        const float* __restrict__ B, int lane){
  float4 a0 = *(const float4*)(A + lane*8);
  float4 a1 = *(const float4*)(A + lane*8 + 4);
  float4 b0 = *(const float4*)(B + lane*8);
  float4 b1 = *(const float4*)(B + lane*8 + 4);
  float s = a0.x*b0.x + a0.y*b0.y + a0.z*b0.z + a0.w*b0.w
          + a1.x*b1.x + a1.y*b1.y + a1.z*b1.z + a1.w*b1.w;
  return wsum(s);
}

// =============== P1: stage-1 folds — pipelined tiled GEMM ===============
// blocks [0,132): 32x32 GEMM tiles, K=256 in two 128-chunks, prefetched.
//   id<112: g=id>>4 (g0 zW@Wq, g1 latW@Wk, g2 codeW@Wk, g3 latW@Wv, g4 codeW@Wv,
//           g5 charts@Wk, g6 charts@Wv), m0=((id&15)>>3)*32, n0=(id&7)*32
//   112..127: g7 Wo@formW (8 Mtiles x 2 Ntiles)
//   128..131: g8 formW^T@formW (2x2)
// then: [132,137) biases | 137 anchors | [138,202) ceff
__global__ __launch_bounds__(256) void p_kernel(
  const float* __restrict__ zW,   const float* __restrict__ latW, const float* __restrict__ codeW,
  const float* __restrict__ Wq,   const float* __restrict__ Wk,   const float* __restrict__ Wv,
  const float* __restrict__ Wo,   const float* __restrict__ cemb, const float* __restrict__ acemb,
  const float* __restrict__ formW,const float* __restrict__ zb,   const float* __restrict__ latb,
  const float* __restrict__ codeb,const float* __restrict__ canch,const float* __restrict__ acanch,
  const float* __restrict__ ctrl, const float* __restrict__ ecov, const float* __restrict__ formb)
{
  __shared__ float As[32*129];                // [r][kk], odd stride -> conflict-free
  __shared__ __align__(16) float Bs[128*36];  // [kk][c], stride 36 float4-aligned
  int blk = blockIdx.x;
  const int t = threadIdx.x;

  if (blk < 132){
    int g, m0, n0;
    if (blk < 112){ g = blk>>4; int s = blk&15; m0 = (s>>3)*32; n0 = (s&7)*32; }
    else if (blk < 128){ g = 7; int s = blk-112; m0 = (s>>1)*32; n0 = (s&1)*32; }
    else { g = 8; int s = blk-128; m0 = (s>>1)*32; n0 = (s&1)*32; }

    const float* Bm = (g==0)? Wq : (g==1||g==2||g==5)? Wk
                    : (g>=7)? formW : Wv;
    const int ldb = (g>=7)? 64 : 256;

    const int rr = t&31, cw = (t>>5)*4;
    const int r2 = t>>3, kg = (t&7)*16, c4 = (t&7)*4;

    // resolve A row pointer once (non-g8 path)
    const float* Ap = cemb; bool avalid = true;
    if (g != 8){
      int grow = m0 + r2;
      if (g==0) Ap = zW + grow*256;
      else if (g==1||g==3) Ap = latW + grow*256;
      else if (g==2||g==4) Ap = codeW + grow*256;
      else if (g==7) Ap = Wo + grow*256;
      else {
        if (grow < 32) Ap = cemb + grow*256;
        else if (grow < 48) Ap = acemb + (grow-32)*256;
        else avalid = false;
      }
    }

    float4 apf[4], bpf[4];
    float apf_s[16];

    auto loadA = [&](int k0){
      if (g==8){
        #pragma unroll
        for (int p=0;p<16;p++){
          int idx = t + p*256; int kk = idx>>5, r = idx&31;
          apf_s[p] = formW[(k0+kk)*64 + m0 + r];
        }
      } else {
        #pragma unroll
        for (int j=0;j<4;j++)
          apf[j] = avalid ? *(const float4*)(Ap + k0 + kg + 4*j) : make_float4(0,0,0,0);
      }
    };
    auto storeA = [&](){
      if (g==8){
        #pragma unroll
        for (int p=0;p<16;p++){
          int idx = t + p*256; int kk = idx>>5, r = idx&31;
          As[r*129 + kk] = apf_s[p];
        }
      } else {
        float* a = As + r2*129 + kg;
        #pragma unroll
        for (int j=0;j<4;j++){
          a[4*j+0]=apf[j].x; a[4*j+1]=apf[j].y; a[4*j+2]=apf[j].z; a[4*j+3]=apf[j].w;
        }
      }
    };
    auto loadB = [&](int k0){
      #pragma unroll
      for (int p=0;p<4;p++){
        int kk = (t + p*256)>>3;
        bpf[p] = *(const float4*)(Bm + (size_t)(k0+kk)*ldb + n0 + c4);
      }
    };
    auto storeB = [&](){
      #pragma unroll
      for (int p=0;p<4;p++){
        int kk = (t + p*256)>>3;
        *(float4*)(Bs + kk*36 + c4) = bpf[p];
      }
    };

    float acc0=0.f, acc1=0.f, acc2=0.f, acc3=0.f;
    auto compute = [&](){
      #pragma unroll 8
      for (int kk=0;kk<128;kk++){
        float av = As[rr*129 + kk];
        float4 bv = *(const float4*)(Bs + kk*36 + cw);
        acc0 += av*bv.x; acc1 += av*bv.y; acc2 += av*bv.z; acc3 += av*bv.w;
      }
    };

    loadA(0);  loadB(0);
    storeA();  storeB();
    __syncthreads();
    loadA(128); loadB(128);     // prefetch chunk 1 (overlaps chunk-0 compute)
    compute();
    __syncthreads();
    storeA();  storeB();
    __syncthreads();
    compute();

    int grow = m0 + rr, gcol = n0 + cw;
    if (g<=4){
      const int off[5] = {0,1,3,2,4};   // g -> g_M5 slot (Zq,Lk,Ck,Lv,Cv order fix)
      *(float4*)(g_M5 + off[g]*(ND*NDM) + grow*NDM + gcol) = make_float4(acc0,acc1,acc2,acc3);
    } else if (g==5||g==6){
      if (grow < 48){
        float* C = (grow<32) ? ((g==5)? g_KC : g_VC) + grow*NDM + gcol
                             : ((g==5)? g_AKC : g_AVC) + (grow-32)*NDM + gcol;
        *(float4*)C = make_float4(acc0,acc1,acc2,acc3);
      }
    } else if (g==7){
      g_M2T2[(gcol+0)*NDM + grow] = acc0;
      g_M2T2[(gcol+1)*NDM + grow] = acc1;
      g_M2T2[(gcol+2)*NDM + grow] = acc2;
      g_M2T2[(gcol+3)*NDM + grow] = acc3;
    } else {
      *(float4*)(g_G + grow*ND + gcol) = make_float4(acc0,acc1,acc2,acc3);
    }
    return;
  }
  blk -= 132;
  if (blk < 5) {                  // folded bias vectors
    const float* vv = (blk==0)? zb : (blk<3 ? latb : codeb);
    const float* Bm = (blk==0)? Wq : ((blk==1||blk==3)? Wk : Wv);
    float s = 0.f;
    #pragma unroll 8
    for (int i=0;i<NDM;i++) s += vv[i]*Bm[i*NDM+t];
    g_B6[blk*NDM+t] = s;
    return;
  }
  blk -= 5;
  if (blk < 1) {                  // anchor norms
    if (t < 32) {
      float s=0.f;
      for (int i=0;i<ND;i++){ float v=canch[t*ND+i]; s+=v*v; }
      g_an2[t]=s;
    } else if (t < 48) {
      int k=t-32; float s=0.f;
      for (int i=0;i<ND;i++){ float v=acanch[k*ND+i]; s+=v*v; }
      g_aan2[k]=s;
    }
    return;
  }
  blk -= 1;
  {                               // 64 blocks: ceff + form_b.ceff
    int w = t>>5, lane = t&31;
    #pragma unroll 1
    for (int rr2=0; rr2<8; rr2++){
      int row = blk*64 + w*8 + rr2;
      float e0=ecov[row*ND+lane], e1=ecov[row*ND+32+lane];
      float c0=ctrl[row*ND+lane], c1=ctrl[row*ND+32+lane];
      float ee = wsum(e0*e0+e1*e1);
      float ec = wsum(e0*c0+e1*c1);
      float k  = (ee > 1e-8f) ? ec/fmaxf(ee,1e-8f) : 0.f;
      float f0 = c0 - k*e0, f1 = c1 - k*e1;
      g_Ceff[row*ND+lane]    = f0;
      g_Ceff[row*ND+32+lane] = f1;
      float fb = wsum(formb[lane]*f0 + formb[lane+32]*f1);
      if (!lane) g_FbC[row] = fb;
    }
  }
}

// =============== P2S: stage-2 folds + sigma (block 257) ===============
__global__ __launch_bounds__(256) void p2s_kernel(
  const float* __restrict__ canch, const float* __restrict__ acanch)
{
  __shared__ __align__(16) float sA[4096];
  __shared__ __align__(16) float sB[4096];
  __shared__ float sv[64];
  const int b_ = blockIdx.x, t = threadIdx.x, w = t>>5, lane = t&31;
  const float* Zq = g_M5;
  const float* Lk = g_M5 + 1*ND*NDM;
  const float* Lv = g_M5 + 2*ND*NDM;
  const float* Ck = g_M5 + 3*ND*NDM;
  const float* Cv = g_M5 + 4*ND*NDM;

  if (b_ < 256){
    int y = b_>>6, i = b_&63;
    float* Orow = g_M4 + (y*ND + i)*NC;
    if (y==0){
      const float* A0 = Zq + i*NDM;
      if (t < 48) Orow[48+t] = (t<16)? acanch[t*ND+i] : canch[(t-16)*ND+i];
      for (int jj=w; jj<50; jj+=8){
        const float* B = (jj<16)? g_AKC+jj*NDM : (jj<48)? g_KC+(jj-16)*NDM
                       : (jj==48)? g_B6+NDM : g_B6+3*NDM;
        float s = dot256(A0, B, lane);
        if (!lane) Orow[(jj<48)? jj : 48+jj] = s;   // 48->96, 49->97
      }
    } else if (y<=2){
      const float* Ki = ((y==1)? Lk : Ck) + i*NDM;
      const float* Vi = ((y==1)? Lv : Cv) + i*NDM;
      for (int jj=w; jj<129; jj+=8){
        const float* A; const float* B;
        if (jj<64)       { A=Ki; B=Zq + jj*NDM; }
        else if (jj<128) { A=Vi; B=g_M2T2 + (jj-64)*NDM; }
        else             { A=Ki; B=g_B6; }
        float s = dot256(A, B, lane);
        if (!lane) Orow[jj] = s;
      }
    } else {
      const float* A0 = g_M2T2 + i*NDM;
      for (int jj=w; jj<50; jj+=8){
        const float* B = (jj<16)? g_AVC+jj*NDM : (jj<48)? g_VC+(jj-16)*NDM
                       : (jj==48)? g_B6+2*NDM : g_B6+4*NDM;
        float s = dot256(A0, B, lane);
        if (!lane) Orow[jj] = s;
      }
    }
    return;
  }
  if (b_ == 256){                 // biases
    for (int idx=t; idx<4*NC; idx+=256) g_bz[idx] = 0.f;
    __syncthreads();
    for (int jj=w; jj<50; jj+=8){
      const float* B = (jj<16)? g_AKC+jj*NDM : (jj<48)? g_KC+(jj-16)*NDM
                     : (jj==48)? g_B6+NDM : g_B6+3*NDM;
      float s = dot256(g_B6, B, lane);
      if (!lane) g_bz[(jj<48)? jj : 48+jj] = s;
    }
    return;
  }
  // ---- block 257: sigma = 3 register-tiled squarings (G^8) + 10 power iters + Rayleigh ----
  #pragma unroll
  for (int r=0;r<16;r++) sA[t+r*256] = g_G[t+r*256];
  __syncthreads();
  const int pr = (t>>4)*4, pc = (t&15)*4;
  for (int sq=0; sq<3; sq++){
    float4 ac0=make_float4(0,0,0,0), ac1=ac0, ac2=ac0, ac3=ac0;
    #pragma unroll 4
    for (int q=0;q<64;q++){
      float4 bv = *(const float4*)(sA + q*64 + pc);
      float a0=sA[(pr+0)*64+q], a1=sA[(pr+1)*64+q], a2=sA[(pr+2)*64+q], a3=sA[(pr+3)*64+q];
      ac0.x+=a0*bv.x; ac0.y+=a0*bv.y; ac0.z+=a0*bv.z; ac0.w+=a0*bv.w;
      ac1.x+=a1*bv.x; ac1.y+=a1*bv.y; ac1.z+=a1*bv.z; ac1.w+=a1*bv.w;
      ac2.x+=a2*bv.x; ac2.y+=a2*bv.y; ac2.z+=a2*bv.z; ac2.w+=a2*bv.w;
      ac3.x+=a3*bv.x; ac3.y+=a3*bv.y; ac3.z+=a3*bv.z; ac3.w+=a3*bv.w;
    }
    __syncthreads();
    *(float4*)(sB+(pr+0)*64+pc)=ac0; *(float4*)(sB+(pr+1)*64+pc)=ac1;
    *(float4*)(sB+(pr+2)*64+pc)=ac2; *(float4*)(sB+(pr+3)*64+pc)=ac3;
    __syncthreads();
    #pragma unroll
    for (int k=0;k<4;k++) ((float4*)sA)[t*4+k] = ((const float4*)sB)[t*4+k];
    __syncthreads();
  }
  if (t < 32){
    sv[lane]=1.f; sv[lane+32]=1.f; __syncwarp();
    for (int it=0; it<10; it++){
      float y0=0.f, y1=0.f;
      for (int q=0;q<64;q++){ float vq=sv[q]; y0+=sA[q*64+lane]*vq; y1+=sA[q*64+32+lane]*vq; }
      float rn = rsqrtf(wsum(y0*y0+y1*y1));
      sv[lane]=y0*rn; sv[lane+32]=y1*rn; __syncwarp();
    }
    float p0=0.f, p1=0.f;       // Rayleigh on ORIGINAL G
    for (int q=0;q<64;q++){ float vq=sv[q]; p0+=g_G[lane*64+q]*vq; p1+=g_G[(lane+32)*64+q]*vq; }
    float lam = wsum(p0*sv[lane]+p1*sv[lane+32]);
    if (!lane) g_inv_sigma = 1.f/fmaxf(sqrtf(fmaxf(lam,0.f)),1e-8f);
  }
}

// =============== GF: fused GEMM-tile + attention + epilogue ===============
// 256 blocks x 512 threads, 16 batches/block. smem: xsT 20.5KB + sg 26.6KB = 47.1KB
#define SG_STRIDE 416   // col offsets: y0=0 (98), y1=98 (129), y2=227 (129), y3=356 (50)
__global__ __launch_bounds__(512) void gf_kernel(
  const float* __restrict__ z,  const float* __restrict__ rw,
  const float* __restrict__ az, const float* __restrict__ arw,
  const float* __restrict__ acz, float* __restrict__ out)
{
  __shared__ __align__(16) float xsT[4*64*20];        // [y][i][bb], bb stride 20
  __shared__ float sg[16*SG_STRIDE];                  // [bat][col]
  const int t = threadIdx.x;
  const int b0 = blockIdx.x*16;

  // load X^T tiles: y in {z, az, acz, Ceff}
  for (int idx=t; idx<4096; idx+=512){
    int y = idx>>10, r = idx&1023, bb = r>>6, i = r&63;
    const float* X = (y==0)? z : (y==1)? az : (y==2)? acz : g_Ceff;
    xsT[(y*64+i)*20 + bb] = X[(b0+bb)*ND + i];
  }
  __syncthreads();

  // GEMM phase: thread -> (y, col)
  if (t < 406){
    int y, col;
    if (t<98){y=0;col=t;} else if (t<227){y=1;col=t-98;}
    else if (t<356){y=2;col=t-227;} else {y=3;col=t-356;}
    const float* M  = g_M4 + (y*ND)*NC + col;
    const float* xb = xsT + (y*64)*20;
    float a0=0,a1=0,a2=0,a3=0,a4=0,a5=0,a6=0,a7=0,a8=0,a9=0,aa=0,ab=0,ac=0,ad=0,ae=0,af=0;
    #pragma unroll 4
    for (int i=0;i<64;i++){
      float mv = M[(size_t)i*NC];
      const float4* x4 = (const float4*)(xb + i*20);
      float4 v0=x4[0], v1=x4[1], v2=x4[2], v3=x4[3];
      a0+=mv*v0.x; a1+=mv*v0.y; a2+=mv*v0.z; a3+=mv*v0.w;
      a4+=mv*v1.x; a5+=mv*v1.y; a6+=mv*v1.z; a7+=mv*v1.w;
      a8+=mv*v2.x; a9+=mv*v2.y; aa+=mv*v2.z; ab+=mv*v2.w;
      ac+=mv*v3.x; ad+=mv*v3.y; ae+=mv*v3.z; af+=mv*v3.w;
    }
    float bz = g_bz[y*NC+col];
    sg[ 0*SG_STRIDE+t]=a0+bz; sg[ 1*SG_STRIDE+t]=a1+bz;
    sg[ 2*SG_STRIDE+t]=a2+bz; sg[ 3*SG_STRIDE+t]=a3+bz;
    sg[ 4*SG_STRIDE+t]=a4+bz; sg[ 5*SG_STRIDE+t]=a5+bz;
    sg[ 6*SG_STRIDE+t]=a6+bz; sg[ 7*SG_STRIDE+t]=a7+bz;
    sg[ 8*SG_STRIDE+t]=a8+bz; sg[ 9*SG_STRIDE+t]=a9+bz;
    sg[10*SG_STRIDE+t]=aa+bz; sg[11*SG_STRIDE+t]=ab+bz;
    sg[12*SG_STRIDE+t]=ac+bz; sg[13*SG_STRIDE+t]=ad+bz;
    sg[14*SG_STRIDE+t]=ae+bz; sg[15*SG_STRIDE+t]=af+bz;
  }
  __syncthreads();

  // attention phase: warp w -> batch b0+w
  const int w = t>>5, lane = t&31;
  const int b = b0 + w;
  const float* gz   = sg + w*SG_STRIDE;
  const float* gaz  = gz + 98;
  const float* gacz = gz + 227;
  const float* gc   = gz + 356;

  float z0  = z[b*ND+lane],   z1  = z[b*ND+32+lane];
  float a0  = az[b*ND+lane],  a1  = az[b*ND+32+lane];
  float c0  = acz[b*ND+lane], c1  = acz[b*ND+32+lane];
  float ce0 = g_Ceff[b*ND+lane], ce1 = g_Ceff[b*ND+32+lane];

  float d_z2   = wsum(z0*z0 + z1*z1);
  float d_zaz  = wsum(z0*a0 + z1*a1);
  float d_az2  = wsum(a0*a0 + a1*a1);
  float d_zacz = wsum(z0*c0 + z1*c1);
  float d_acz2 = wsum(c0*c0 + c1*c1);
  float d_zy1  = wsum(z0*gaz[lane]     + z1*gaz[32+lane]);
  float d_zy2  = wsum(z0*gacz[lane]    + z1*gacz[32+lane]);
  float d_cy3  = wsum(ce0*gaz[64+lane] + ce1*gaz[96+lane]);
  float d_cy4  = wsum(ce0*gacz[64+lane]+ ce1*gacz[96+lane]);

  float s0, t0, s1 = -1e30f, t1 = 0.f;
  {
    int tok = lane;
    if (tok == 0){
      s0 = (d_zy1 + gz[96] + gaz[128])*0.0625f - (d_z2 - 2.f*d_zaz + d_az2);
      t0 = d_cy3 + gc[48];
    } else if (tok == 1){
      s0 = (d_zy2 + gz[97] + gacz[128])*0.0625f - (d_z2 - 2.f*d_zacz + d_acz2);
      t0 = d_cy4 + gc[49];
    } else if (tok < 18){
      int k = tok-2; float aw = arw[b*NKA+k];
      s0 = aw*gz[k]*0.0625f - (d_z2 - 2.f*gz[48+k] + g_aan2[k]);
      t0 = aw*gc[k];
    } else {
      int k = tok-18; float cw = rw[b*NK+k];
      s0 = cw*gz[16+k]*0.0625f - (d_z2 - 2.f*gz[64+k] + g_an2[k]);
      t0 = cw*gc[16+k];
    }
  }
  if (lane < 18){
    int k = lane + 14;     // token lane+32 = chart k = lane+14
    float cw = rw[b*NK+k];
    s1 = cw*gz[16+k]*0.0625f - (d_z2 - 2.f*gz[64+k] + g_an2[k]);
    t1 = cw*gc[16+k];
  }

  float m = wmax(fmaxf(s0, s1));
  float e0 = __expf(s0 - m);
  float e1 = (lane < 18) ? __expf(s1 - m) : 0.f;
  float den = wsum(e0 + e1);
  float num = wsum(e0*t0 + e1*t1);
  if (!lane) out[b] = g_inv_sigma * num / den + g_FbC[b];
}

// =============== launch ===============
extern "C" void kernel_launch(void* const* d_in, const int* in_sizes, int n_in,
                              void* d_out, int out_size)
{
  const float* z     =(const float*)d_in[0];
  const float* rw    =(const float*)d_in[1];
  const float* az    =(const float*)d_in[2];
  const float* arw   =(const float*)d_in[3];
  const float* acz   =(const float*)d_in[4];
  const float* ctrl  =(const float*)d_in[5];
  const float* ecov  =(const float*)d_in[6];
  const float* cemb  =(const float*)d_in[7];
  const float* canch =(const float*)d_in[8];
  const float* acemb =(const float*)d_in[9];
  const float* acanch=(const float*)d_in[10];
  const float* zW    =(const float*)d_in[11];
  const float* zb    =(const float*)d_in[12];
  const float* latW  =(const float*)d_in[13];
  const float* latb  =(const float*)d_in[14];
  const float* codeW =(const float*)d_in[15];
  const float* codeb =(const float*)d_in[16];
  const float* Wq    =(const float*)d_in[17];
  const float* Wk    =(const float*)d_in[18];
  const float* Wv    =(const float*)d_in[19];
  const float* Wo    =(const float*)d_in[20];
  const float* formW =(const float*)d_in[21];
  const float* formb =(const float*)d_in[22];
  float* out = (float*)d_out;

  p_kernel<<<202,256>>>(zW,latW,codeW,Wq,Wk,Wv,Wo,cemb,acemb,formW,
                        zb,latb,codeb,canch,acanch,ctrl,ecov,formb);
  p2s_kernel<<<258,256>>>(canch,acanch);
  gf_kernel<<<256,512>>>(z,rw,az,arw,acz,out);
}

// round 11
// speedup vs baseline: 3.5982x; 1.0155x over previous
#include <cuda_runtime.h>
#include <cuda_bf16.h>

#define NB  4096
#define ND  64
#define NDM 256
#define NK  32
#define NKA 16
#define NC  160   // M4 row stride (padded); active cols per y: 98,129,129,50

// ----- device scratch (16B aligned for float4) -----
__device__ __align__(16) float g_M5[5*ND*NDM];   // Zq, Lk, Lv, Ck, Cv
__device__ __align__(16) float g_B6[5*NDM];      // bq, bLk, bLv, bCk, bCv
__device__ __align__(16) float g_KC[NK*NDM], g_VC[NK*NDM];
__device__ __align__(16) float g_AKC[NKA*NDM], g_AVC[NKA*NDM];
__device__ float g_an2[NK], g_aan2[NKA];
__device__ __align__(16) float g_M2T2[ND*NDM];   // (Wo@form_W)^T : [d][j]
__device__ __align__(16) float g_G[ND*ND];       // form_W^T form_W
__device__ float g_inv_sigma;
__device__ __align__(16) float g_M4[4*ND*NC];    // folded GEMM matrices
__device__ __align__(16) float g_bz[4*NC];

__device__ __forceinline__ float wsum(float v){
  #pragma unroll
  for(int o=16;o>0;o>>=1) v += __shfl_xor_sync(0xffffffffu,v,o);
  return v;
}
__device__ __forceinline__ float wmax(float v){
  #pragma unroll
  for(int o=16;o>0;o>>=1) v = fmaxf(v,__shfl_xor_sync(0xffffffffu,v,o));
  return v;
}
// warp dot of two 256-float vectors, both 16B aligned
__device__ __forceinline__ float dot256(const float* __restrict__ A,
                                        const float* __restrict__ B, int lane){
  float4 a0 = *(const float4*)(A + lane*8);
  float4 a1 = *(const float4*)(A + lane*8 + 4);
  float4 b0 = *(const float4*)(B + lane*8);
  float4 b1 = *(const float4*)(B + lane*8 + 4);
  float s = a0.x*b0.x + a0.y*b0.y + a0.z*b0.z + a0.w*b0.w
          + a1.x*b1.x + a1.y*b1.y + a1.z*b1.z + a1.w*b1.w;
  return wsum(s);
}

// =============== P1: stage-1 folds — pipelined tiled GEMM, 1 wave ===============
// blocks [0,132): 32x32 GEMM tiles (as R10) | [132,137) biases | 137 anchors
__global__ __launch_bounds__(256) void p_kernel(
  const float* __restrict__ zW,   const float* __restrict__ latW, const float* __restrict__ codeW,
  const float* __restrict__ Wq,   const float* __restrict__ Wk,   const float* __restrict__ Wv,
  const float* __restrict__ Wo,   const float* __restrict__ cemb, const float* __restrict__ acemb,
  const float* __restrict__ formW,const float* __restrict__ zb,   const float* __restrict__ latb,
  const float* __restrict__ codeb,const float* __restrict__ canch,const float* __restrict__ acanch)
{
  __shared__ float As[32*129];                // [r][kk], odd stride -> conflict-free
  __shared__ __align__(16) float Bs[128*36];  // [kk][c], stride 36 float4-aligned
  int blk = blockIdx.x;
  const int t = threadIdx.x;

  if (blk < 132){
    int g, m0, n0;
    if (blk < 112){ g = blk>>4; int s = blk&15; m0 = (s>>3)*32; n0 = (s&7)*32; }
    else if (blk < 128){ g = 7; int s = blk-112; m0 = (s>>1)*32; n0 = (s&1)*32; }
    else { g = 8; int s = blk-128; m0 = (s>>1)*32; n0 = (s&1)*32; }

    const float* Bm = (g==0)? Wq : (g==1||g==2||g==5)? Wk
                    : (g>=7)? formW : Wv;
    const int ldb = (g>=7)? 64 : 256;

    const int rr = t&31, cw = (t>>5)*4;
    const int r2 = t>>3, kg = (t&7)*16, c4 = (t&7)*4;

    const float* Ap = cemb; bool avalid = true;
    if (g != 8){
      int grow = m0 + r2;
      if (g==0) Ap = zW + grow*256;
      else if (g==1||g==3) Ap = latW + grow*256;
      else if (g==2||g==4) Ap = codeW + grow*256;
      else if (g==7) Ap = Wo + grow*256;
      else {
        if (grow < 32) Ap = cemb + grow*256;
        else if (grow < 48) Ap = acemb + (grow-32)*256;
        else avalid = false;
      }
    }

    float4 apf[4], bpf[4];
    float apf_s[16];

    auto loadA = [&](int k0){
      if (g==8){
        #pragma unroll
        for (int p=0;p<16;p++){
          int idx = t + p*256; int kk = idx>>5, r = idx&31;
          apf_s[p] = formW[(k0+kk)*64 + m0 + r];
        }
      } else {
        #pragma unroll
        for (int j=0;j<4;j++)
          apf[j] = avalid ? *(const float4*)(Ap + k0 + kg + 4*j) : make_float4(0,0,0,0);
      }
    };
    auto storeA = [&](){
      if (g==8){
        #pragma unroll
        for (int p=0;p<16;p++){
          int idx = t + p*256; int kk = idx>>5, r = idx&31;
          As[r*129 + kk] = apf_s[p];
        }
      } else {
        float* a = As + r2*129 + kg;
        #pragma unroll
        for (int j=0;j<4;j++){
          a[4*j+0]=apf[j].x; a[4*j+1]=apf[j].y; a[4*j+2]=apf[j].z; a[4*j+3]=apf[j].w;
        }
      }
    };
    auto loadB = [&](int k0){
      #pragma unroll
      for (int p=0;p<4;p++){
        int kk = (t + p*256)>>3;
        bpf[p] = *(const float4*)(Bm + (size_t)(k0+kk)*ldb + n0 + c4);
      }
    };
    auto storeB = [&](){
      #pragma unroll
      for (int p=0;p<4;p++){
        int kk = (t + p*256)>>3;
        *(float4*)(Bs + kk*36 + c4) = bpf[p];
      }
    };

    float acc0=0.f, acc1=0.f, acc2=0.f, acc3=0.f;
    auto compute = [&](){
      #pragma unroll 8
      for (int kk=0;kk<128;kk++){
        float av = As[rr*129 + kk];
        float4 bv = *(const float4*)(Bs + kk*36 + cw);
        acc0 += av*bv.x; acc1 += av*bv.y; acc2 += av*bv.z; acc3 += av*bv.w;
      }
    };

    loadA(0);  loadB(0);
    storeA();  storeB();
    __syncthreads();
    loadA(128); loadB(128);     // prefetch chunk 1 (overlaps chunk-0 compute)
    compute();
    __syncthreads();
    storeA();  storeB();
    __syncthreads();
    compute();

    int grow = m0 + rr, gcol = n0 + cw;
    if (g<=4){
      const int off[5] = {0,1,3,2,4};   // g -> g_M5 slot (Zq,Lk,Ck,Lv,Cv order fix)
      *(float4*)(g_M5 + off[g]*(ND*NDM) + grow*NDM + gcol) = make_float4(acc0,acc1,acc2,acc3);
    } else if (g==5||g==6){
      if (grow < 48){
        float* C = (grow<32) ? ((g==5)? g_KC : g_VC) + grow*NDM + gcol
                             : ((g==5)? g_AKC : g_AVC) + (grow-32)*NDM + gcol;
        *(float4*)C = make_float4(acc0,acc1,acc2,acc3);
      }
    } else if (g==7){
      g_M2T2[(gcol+0)*NDM + grow] = acc0;
      g_M2T2[(gcol+1)*NDM + grow] = acc1;
      g_M2T2[(gcol+2)*NDM + grow] = acc2;
      g_M2T2[(gcol+3)*NDM + grow] = acc3;
    } else {
      *(float4*)(g_G + grow*ND + gcol) = make_float4(acc0,acc1,acc2,acc3);
    }
    return;
  }
  blk -= 132;
  if (blk < 5) {                  // folded bias vectors
    const float* vv = (blk==0)? zb : (blk<3 ? latb : codeb);
    const float* Bm = (blk==0)? Wq : ((blk==1||blk==3)? Wk : Wv);
    float s = 0.f;
    #pragma unroll 16
    for (int i=0;i<NDM;i++) s += vv[i]*Bm[i*NDM+t];
    g_B6[blk*NDM+t] = s;
    return;
  }
  // anchor norms
  if (t < 32) {
    float s=0.f;
    for (int i=0;i<ND;i++){ float v=canch[t*ND+i]; s+=v*v; }
    g_an2[t]=s;
  } else if (t < 48) {
    int k=t-32; float s=0.f;
    for (int i=0;i<ND;i++){ float v=acanch[k*ND+i]; s+=v*v; }
    g_aan2[k]=s;
  }
}

// =============== P2S: sigma (block 0) + biases (block 1) + stage-2 rows (2..257) ===============
__global__ __launch_bounds__(256) void p2s_kernel(
  const float* __restrict__ canch, const float* __restrict__ acanch)
{
  __shared__ __align__(16) float sA[4096];
  __shared__ __align__(16) float sB[4096];
  __shared__ float sv[64];
  const int b_ = blockIdx.x, t = threadIdx.x, w = t>>5, lane = t&31;
  const float* Zq = g_M5;
  const float* Lk = g_M5 + 1*ND*NDM;
  const float* Lv = g_M5 + 2*ND*NDM;
  const float* Ck = g_M5 + 3*ND*NDM;
  const float* Cv = g_M5 + 4*ND*NDM;

  if (b_ == 0){
    // ---- sigma: 3 register-tiled squarings (G^8) + 10 power iters + Rayleigh ----
    #pragma unroll
    for (int r=0;r<16;r++) sA[t+r*256] = g_G[t+r*256];
    __syncthreads();
    const int pr = (t>>4)*4, pc = (t&15)*4;
    for (int sq=0; sq<3; sq++){
      float4 ac0=make_float4(0,0,0,0), ac1=ac0, ac2=ac0, ac3=ac0;
      #pragma unroll 4
      for (int q=0;q<64;q++){
        float4 bv = *(const float4*)(sA + q*64 + pc);
        float a0=sA[(pr+0)*64+q], a1=sA[(pr+1)*64+q], a2=sA[(pr+2)*64+q], a3=sA[(pr+3)*64+q];
        ac0.x+=a0*bv.x; ac0.y+=a0*bv.y; ac0.z+=a0*bv.z; ac0.w+=a0*bv.w;
        ac1.x+=a1*bv.x; ac1.y+=a1*bv.y; ac1.z+=a1*bv.z; ac1.w+=a1*bv.w;
        ac2.x+=a2*bv.x; ac2.y+=a2*bv.y; ac2.z+=a2*bv.z; ac2.w+=a2*bv.w;
        ac3.x+=a3*bv.x; ac3.y+=a3*bv.y; ac3.z+=a3*bv.z; ac3.w+=a3*bv.w;
      }
      __syncthreads();
      *(float4*)(sB+(pr+0)*64+pc)=ac0; *(float4*)(sB+(pr+1)*64+pc)=ac1;
      *(float4*)(sB+(pr+2)*64+pc)=ac2; *(float4*)(sB+(pr+3)*64+pc)=ac3;
      __syncthreads();
      #pragma unroll
      for (int k=0;k<4;k++) ((float4*)sA)[t*4+k] = ((const float4*)sB)[t*4+k];
      __syncthreads();
    }
    if (t < 32){
      sv[lane]=1.f; sv[lane+32]=1.f; __syncwarp();
      for (int it=0; it<10; it++){
        float y0=0.f, y1=0.f;
        for (int q=0;q<64;q++){ float vq=sv[q]; y0+=sA[q*64+lane]*vq; y1+=sA[q*64+32+lane]*vq; }
        float rn = rsqrtf(wsum(y0*y0+y1*y1));
        sv[lane]=y0*rn; sv[lane+32]=y1*rn; __syncwarp();
      }
      float p0=0.f, p1=0.f;     // Rayleigh on ORIGINAL G
      for (int q=0;q<64;q++){ float vq=sv[q]; p0+=g_G[lane*64+q]*vq; p1+=g_G[(lane+32)*64+q]*vq; }
      float lam = wsum(p0*sv[lane]+p1*sv[lane+32]);
      if (!lane) g_inv_sigma = 1.f/fmaxf(sqrtf(fmaxf(lam,0.f)),1e-8f);
    }
    return;
  }
  if (b_ == 1){                   // biases
    for (int idx=t; idx<4*NC; idx+=256) g_bz[idx] = 0.f;
    __syncthreads();
    for (int jj=w; jj<50; jj+=8){
      const float* B = (jj<16)? g_AKC+jj*NDM : (jj<48)? g_KC+(jj-16)*NDM
                     : (jj==48)? g_B6+NDM : g_B6+3*NDM;
      float s = dot256(g_B6, B, lane);
      if (!lane) g_bz[(jj<48)? jj : 48+jj] = s;
    }
    return;
  }
  {
    int row = b_ - 2;             // 0..255
    int y = row>>6, i = row&63;
    float* Orow = g_M4 + (y*ND + i)*NC;
    if (y==0){
      const float* A0 = Zq + i*NDM;
      if (t < 48) Orow[48+t] = (t<16)? acanch[t*ND+i] : canch[(t-16)*ND+i];
      for (int jj=w; jj<50; jj+=8){
        const float* B = (jj<16)? g_AKC+jj*NDM : (jj<48)? g_KC+(jj-16)*NDM
                       : (jj==48)? g_B6+NDM : g_B6+3*NDM;
        float s = dot256(A0, B, lane);
        if (!lane) Orow[(jj<48)? jj : 48+jj] = s;   // 48->96, 49->97
      }
    } else if (y<=2){
      const float* Ki = ((y==1)? Lk : Ck) + i*NDM;
      const float* Vi = ((y==1)? Lv : Cv) + i*NDM;
      for (int jj=w; jj<129; jj+=8){
        const float* A; const float* B;
        if (jj<64)       { A=Ki; B=Zq + jj*NDM; }
        else if (jj<128) { A=Vi; B=g_M2T2 + (jj-64)*NDM; }
        else             { A=Ki; B=g_B6; }
        float s = dot256(A, B, lane);
        if (!lane) Orow[jj] = s;
      }
    } else {
      const float* A0 = g_M2T2 + i*NDM;
      for (int jj=w; jj<50; jj+=8){
        const float* B = (jj<16)? g_AVC+jj*NDM : (jj<48)? g_VC+(jj-16)*NDM
                       : (jj==48)? g_B6+2*NDM : g_B6+4*NDM;
        float s = dot256(A0, B, lane);
        if (!lane) Orow[jj] = s;
      }
    }
  }
}

// =============== GF: fused ceff + GEMM-tile + attention + epilogue ===============
// 256 blocks x 512 threads, 16 batches/block. smem: xsT 20.5KB + sg 26.6KB = 47.1KB
#define SG_STRIDE 416   // col offsets: y0=0 (98), y1=98 (129), y2=227 (129), y3=356 (50)
__global__ __launch_bounds__(512) void gf_kernel(
  const float* __restrict__ z,   const float* __restrict__ rw,
  const float* __restrict__ az,  const float* __restrict__ arw,
  const float* __restrict__ acz, const float* __restrict__ ctrl,
  const float* __restrict__ ecov,const float* __restrict__ formb,
  float* __restrict__ out)
{
  __shared__ __align__(16) float xsT[4*64*20];        // [y][i][bb], bb stride 20
  __shared__ float sg[16*SG_STRIDE];                  // [bat][col]
  const int t = threadIdx.x;
  const int b0 = blockIdx.x*16;
  const int w = t>>5, lane = t&31;
  const int b = b0 + w;

  // load X^T tiles for y in {z, az, acz}
  for (int idx=t; idx<3072; idx+=512){
    int y = idx>>10, r = idx&1023, bb = r>>6, i = r&63;
    const float* X = (y==0)? z : (y==1)? az : acz;
    xsT[(y*64+i)*20 + bb] = X[(b0+bb)*ND + i];
  }

  // ceff inline: warp w owns batch b
  float e0=ecov[b*ND+lane], e1=ecov[b*ND+32+lane];
  float c0g=ctrl[b*ND+lane], c1g=ctrl[b*ND+32+lane];
  float ee = wsum(e0*e0+e1*e1);
  float ec = wsum(e0*c0g+e1*c1g);
  float kk = (ee > 1e-8f) ? ec/fmaxf(ee,1e-8f) : 0.f;
  float ce0 = c0g - kk*e0, ce1 = c1g - kk*e1;
  float fb = wsum(formb[lane]*ce0 + formb[lane+32]*ce1);
  xsT[(3*64+lane)*20 + w]    = ce0;
  xsT[(3*64+32+lane)*20 + w] = ce1;
  __syncthreads();

  // GEMM phase: thread -> (y, col)
  if (t < 406){
    int y, col;
    if (t<98){y=0;col=t;} else if (t<227){y=1;col=t-98;}
    else if (t<356){y=2;col=t-227;} else {y=3;col=t-356;}
    const float* M  = g_M4 + (y*ND)*NC + col;
    const float* xb = xsT + (y*64)*20;
    float a0=0,a1=0,a2=0,a3=0,a4=0,a5=0,a6=0,a7=0,a8=0,a9=0,aa=0,ab=0,ac=0,ad=0,ae=0,af=0;
    #pragma unroll 4
    for (int i=0;i<64;i++){
      float mv = M[(size_t)i*NC];
      const float4* x4 = (const float4*)(xb + i*20);
      float4 v0=x4[0], v1=x4[1], v2=x4[2], v3=x4[3];
      a0+=mv*v0.x; a1+=mv*v0.y; a2+=mv*v0.z; a3+=mv*v0.w;
      a4+=mv*v1.x; a5+=mv*v1.y; a6+=mv*v1.z; a7+=mv*v1.w;
      a8+=mv*v2.x; a9+=mv*v2.y; aa+=mv*v2.z; ab+=mv*v2.w;
      ac+=mv*v3.x; ad+=mv*v3.y; ae+=mv*v3.z; af+=mv*v3.w;
    }
    float bz = g_bz[y*NC+col];
    sg[ 0*SG_STRIDE+t]=a0+bz; sg[ 1*SG_STRIDE+t]=a1+bz;
    sg[ 2*SG_STRIDE+t]=a2+bz; sg[ 3*SG_STRIDE+t]=a3+bz;
    sg[ 4*SG_STRIDE+t]=a4+bz; sg[ 5*SG_STRIDE+t]=a5+bz;
    sg[ 6*SG_STRIDE+t]=a6+bz; sg[ 7*SG_STRIDE+t]=a7+bz;
    sg[ 8*SG_STRIDE+t]=a8+bz; sg[ 9*SG_STRIDE+t]=a9+bz;
    sg[10*SG_STRIDE+t]=aa+bz; sg[11*SG_STRIDE+t]=ab+bz;
    sg[12*SG_STRIDE+t]=ac+bz; sg[13*SG_STRIDE+t]=ad+bz;
    sg[14*SG_STRIDE+t]=ae+bz; sg[15*SG_STRIDE+t]=af+bz;
  }
  __syncthreads();

  // attention phase: warp w -> batch b
  const float* gz   = sg + w*SG_STRIDE;
  const float* gaz  = gz + 98;
  const float* gacz = gz + 227;
  const float* gc   = gz + 356;

  float z0  = z[b*ND+lane],   z1  = z[b*ND+32+lane];
  float a0  = az[b*ND+lane],  a1  = az[b*ND+32+lane];
  float c0  = acz[b*ND+lane], c1  = acz[b*ND+32+lane];

  float d_z2   = wsum(z0*z0 + z1*z1);
  float d_zaz  = wsum(z0*a0 + z1*a1);
  float d_az2  = wsum(a0*a0 + a1*a1);
  float d_zacz = wsum(z0*c0 + z1*c1);
  float d_acz2 = wsum(c0*c0 + c1*c1);
  float d_zy1  = wsum(z0*gaz[lane]     + z1*gaz[32+lane]);
  float d_zy2  = wsum(z0*gacz[lane]    + z1*gacz[32+lane]);
  float d_cy3  = wsum(ce0*gaz[64+lane] + ce1*gaz[96+lane]);
  float d_cy4  = wsum(ce0*gacz[64+lane]+ ce1*gacz[96+lane]);

  float s0, t0, s1 = -1e30f, t1 = 0.f;
  {
    int tok = lane;
    if (tok == 0){
      s0 = (d_zy1 + gz[96] + gaz[128])*0.0625f - (d_z2 - 2.f*d_zaz + d_az2);
      t0 = d_cy3 + gc[48];
    } else if (tok == 1){
      s0 = (d_zy2 + gz[97] + gacz[128])*0.0625f - (d_z2 - 2.f*d_zacz + d_acz2);
      t0 = d_cy4 + gc[49];
    } else if (tok < 18){
      int k = tok-2; float aw = arw[b*NKA+k];
      s0 = aw*gz[k]*0.0625f - (d_z2 - 2.f*gz[48+k] + g_aan2[k]);
      t0 = aw*gc[k];
    } else {
      int k = tok-18; float cw = rw[b*NK+k];
      s0 = cw*gz[16+k]*0.0625f - (d_z2 - 2.f*gz[64+k] + g_an2[k]);
      t0 = cw*gc[16+k];
    }
  }
  if (lane < 18){
    int k = lane + 14;     // token lane+32 = chart k = lane+14
    float cw = rw[b*NK+k];
    s1 = cw*gz[16+k]*0.0625f - (d_z2 - 2.f*gz[64+k] + g_an2[k]);
    t1 = cw*gc[16+k];
  }

  float m = wmax(fmaxf(s0, s1));
  float ex0 = __expf(s0 - m);
  float ex1 = (lane < 18) ? __expf(s1 - m) : 0.f;
  float den = wsum(ex0 + ex1);
  float num = wsum(ex0*t0 + ex1*t1);
  if (!lane) out[b] = g_inv_sigma * num / den + fb;
}

// =============== launch ===============
extern "C" void kernel_launch(void* const* d_in, const int* in_sizes, int n_in,
                              void* d_out, int out_size)
{
  const float* z     =(const float*)d_in[0];
  const float* rw    =(const float*)d_in[1];
  const float* az    =(const float*)d_in[2];
  const float* arw   =(const float*)d_in[3];
  const float* acz   =(const float*)d_in[4];
  const float* ctrl  =(const float*)d_in[5];
  const float* ecov  =(const float*)d_in[6];
  const float* cemb  =(const float*)d_in[7];
  const float* canch =(const float*)d_in[8];
  const float* acemb =(const float*)d_in[9];
  const float* acanch=(const float*)d_in[10];
  const float* zW    =(const float*)d_in[11];
  const float* zb    =(const float*)d_in[12];
  const float* latW  =(const float*)d_in[13];
  const float* latb  =(const float*)d_in[14];
  const float* codeW =(const float*)d_in[15];
  const float* codeb =(const float*)d_in[16];
  const float* Wq    =(const float*)d_in[17];
  const float* Wk    =(const float*)d_in[18];
  const float* Wv    =(const float*)d_in[19];
  const float* Wo    =(const float*)d_in[20];
  const float* formW =(const float*)d_in[21];
  const float* formb =(const float*)d_in[22];
  float* out = (float*)d_out;

  p_kernel<<<138,256>>>(zW,latW,codeW,Wq,Wk,Wv,Wo,cemb,acemb,formW,
                        zb,latb,codeb,canch,acanch);
  p2s_kernel<<<258,256>>>(canch,acanch);
  gf_kernel<<<256,512>>>(z,rw,az,arw,acz,ctrl,ecov,formb,out);
}

// round 12
// speedup vs baseline: 3.7761x; 1.0494x over previous
#include <cuda_runtime.h>
#include <cuda_bf16.h>

#define NB  4096
#define ND  64
#define NDM 256
#define NK  32
#define NKA 16
#define NC  160   // M4 row stride; active cols per y: 98,129,129,50

// ----- device scratch -----
__device__ __align__(16) float g_M5[5*ND*NDM];   // Zq, Lk, Lv, Ck, Cv
__device__ __align__(16) float g_B6[5*NDM];      // bq, bLk, bLv, bCk, bCv
__device__ __align__(16) float g_KC[NK*NDM], g_VC[NK*NDM];
__device__ __align__(16) float g_AKC[NKA*NDM], g_AVC[NKA*NDM];
__device__ float g_an2[NK], g_aan2[NKA];
__device__ __align__(16) float g_M2T2[ND*NDM];   // (Wo@form_W)^T : [d][j]
__device__ __align__(16) float g_G[ND*ND];       // form_W^T form_W
__device__ float g_inv_sigma;
__device__ __align__(16) float g_M4[4*ND*NC];    // folded GEMM matrices
__device__ __align__(16) float g_bz[4*NC];

__device__ __forceinline__ float wsum(float v){
  #pragma unroll
  for(int o=16;o>0;o>>=1) v += __shfl_xor_sync(0xffffffffu,v,o);
  return v;
}
__device__ __forceinline__ float wmax(float v){
  #pragma unroll
  for(int o=16;o>0;o>>=1) v = fmaxf(v,__shfl_xor_sync(0xffffffffu,v,o));
  return v;
}
__device__ __forceinline__ float dot256(const float* __restrict__ A,
                                        const float* __restrict__ B, int lane){
  float4 a0 = *(const float4*)(A + lane*8);
  float4 a1 = *(const float4*)(A + lane*8 + 4);
  float4 b0 = *(const float4*)(B + lane*8);
  float4 b1 = *(const float4*)(B + lane*8 + 4);
  float s = a0.x*b0.x + a0.y*b0.y + a0.z*b0.z + a0.w*b0.w
          + a1.x*b1.x + a1.y*b1.y + a1.z*b1.z + a1.w*b1.w;
  return wsum(s);
}

// =============== P1: stage-1 folds — 512-thread 32x32 tiles ===============
// blocks [0,80): g0-g4 (5 matrices x 16 tiles) | [80,112): g5,g6 charts
// [112,128): g7 Wo@formW | [128,132): g8 G | [132,137) biases | 137 anchors
__global__ __launch_bounds__(512) void p_kernel(
  const float* __restrict__ zW,   const float* __restrict__ latW, const float* __restrict__ codeW,
  const float* __restrict__ Wq,   const float* __restrict__ Wk,   const float* __restrict__ Wv,
  const float* __restrict__ Wo,   const float* __restrict__ cemb, const float* __restrict__ acemb,
  const float* __restrict__ formW,const float* __restrict__ zb,   const float* __restrict__ latb,
  const float* __restrict__ codeb,const float* __restrict__ canch,const float* __restrict__ acanch)
{
  __shared__ float As[32*65];
  __shared__ __align__(16) float Bs[64*36];
  int blk = blockIdx.x;
  const int t = threadIdx.x;
  const int w = t>>5, lane = t&31;

  if (blk < 132){
    int g, m0, n0;
    if (blk < 80){ g = blk>>4; int s = blk&15; m0=(s>>3)*32; n0=(s&7)*32; }
    else if (blk < 112){ g = 5 + ((blk-80)>>4); int s=(blk-80)&15; m0=(s>>3)*32; n0=(s&7)*32; }
    else if (blk < 128){ int s=blk-112; g=7; m0=(s>>1)*32; n0=(s&1)*32; }
    else { int s=blk-128; g=8; m0=(s>>1)*32; n0=(s&1)*32; }

    const float* Bm = (g==0)? Wq : (g==1||g==2||g==5)? Wk : (g>=7)? formW : Wv;
    const int ldb = (g>=7)? 64 : 256;

    const int r2 = t>>4, kg = (t&15)*4;
    const float* Ap = cemb; bool avalid = true;
    if (g != 8){
      int grow = m0 + r2;
      if (g==0) Ap = zW + grow*256;
      else if (g==1||g==3) Ap = latW + grow*256;
      else if (g==2||g==4) Ap = codeW + grow*256;
      else if (g==7) Ap = Wo + grow*256;
      else {
        if (grow < 32) Ap = cemb + grow*256;
        else if (grow < 48) Ap = acemb + (grow-32)*256;
        else avalid = false;
      }
    }
    const int kkB = t>>3, cB4 = (t&7)*4;

    float4 apf; float apf_s[4]; float4 bpf;

    auto loadA = [&](int k0){
      if (g==8){
        #pragma unroll
        for (int p=0;p<4;p++){
          int idx = t + p*512, kk = idx>>5, r = idx&31;
          apf_s[p] = formW[(k0+kk)*64 + m0 + r];
        }
      } else apf = avalid ? *(const float4*)(Ap + k0 + kg) : make_float4(0,0,0,0);
    };
    auto storeA = [&](){
      if (g==8){
        #pragma unroll
        for (int p=0;p<4;p++){
          int idx = t + p*512, kk = idx>>5, r = idx&31;
          As[r*65+kk] = apf_s[p];
        }
      } else {
        float* a = As + r2*65 + kg;
        a[0]=apf.x; a[1]=apf.y; a[2]=apf.z; a[3]=apf.w;
      }
    };
    auto loadB = [&](int k0){
      bpf = *(const float4*)(Bm + (size_t)(k0+kkB)*ldb + n0 + cB4);
    };
    auto storeB = [&](){ *(float4*)(Bs + kkB*36 + cB4) = bpf; };

    float acc0=0.f, acc1=0.f;
    const int cw = w*2;
    auto compute = [&](){
      #pragma unroll 8
      for (int kk=0;kk<64;kk++){
        float av = As[lane*65+kk];
        float2 bv = *(const float2*)(Bs + kk*36 + cw);
        acc0 += av*bv.x; acc1 += av*bv.y;
      }
    };

    loadA(0); loadB(0); storeA(); storeB(); __syncthreads();
    #pragma unroll 1
    for (int c=1;c<4;c++){
      loadA(c*64); loadB(c*64);
      compute(); __syncthreads();
      storeA(); storeB(); __syncthreads();
    }
    compute();

    int grow = m0 + lane, gcol = n0 + cw;
    if (g<=4){
      const int off[5] = {0,1,3,2,4};   // Zq,Lk,Ck,Lv,Cv slot order
      *(float2*)(g_M5 + off[g]*(ND*NDM) + grow*NDM + gcol) = make_float2(acc0,acc1);
    } else if (g<=6){
      if (grow < 48){
        float* C = (grow<32) ? ((g==5)? g_KC : g_VC) + grow*NDM + gcol
                             : ((g==5)? g_AKC : g_AVC) + (grow-32)*NDM + gcol;
        *(float2*)C = make_float2(acc0,acc1);
      }
    } else if (g==7){
      g_M2T2[(gcol+0)*NDM + grow] = acc0;
      g_M2T2[(gcol+1)*NDM + grow] = acc1;
    } else {
      *(float2*)(g_G + grow*ND + gcol) = make_float2(acc0,acc1);
    }
    return;
  }
  blk -= 132;
  if (blk < 5) {                  // folded bias vectors, split-K halves
    const float* vv = (blk==0)? zb : (blk<3 ? latb : codeb);
    const float* Bm = (blk==0)? Wq : ((blk==1||blk==3)? Wk : Wv);
    int c = t & 255, h = t >> 8;
    float s = 0.f;
    #pragma unroll 16
    for (int i=h*128; i<h*128+128; i++) s += vv[i]*Bm[i*NDM+c];
    As[t] = s;
    __syncthreads();
    if (t < 256) g_B6[blk*NDM + t] = As[t] + As[256+t];
    return;
  }
  // anchor norms
  if (t < 32) {
    float s=0.f;
    for (int i=0;i<ND;i++){ float v=canch[t*ND+i]; s+=v*v; }
    g_an2[t]=s;
  } else if (t < 48) {
    int k=t-32; float s=0.f;
    for (int i=0;i<ND;i++){ float v=acanch[k*ND+i]; s+=v*v; }
    g_aan2[k]=s;
  }
}

// =============== P2S: sigma | anchors | vectors | 24 GEMM tiles ===============
__global__ __launch_bounds__(512) void p2s_kernel(
  const float* __restrict__ canch, const float* __restrict__ acanch)
{
  __shared__ __align__(16) float sm[8448];   // union: sigma(8256) | tiles(2080+2304)
  const int blk = blockIdx.x, t = threadIdx.x, w = t>>5, lane = t&31;
  const float* Zq = g_M5;
  const float* Lk = g_M5 + 1*ND*NDM;
  const float* Lv = g_M5 + 2*ND*NDM;
  const float* Ck = g_M5 + 3*ND*NDM;
  const float* Cv = g_M5 + 4*ND*NDM;

  if (blk == 0){
    // ---- sigma: 3 squarings (G^8) + 10 power iters + Rayleigh ----
    float* sA = sm; float* sB = sm + 4096; float* sv = sm + 8192;
    #pragma unroll
    for (int r=0;r<8;r++) sA[t + r*512] = g_G[t + r*512];
    __syncthreads();
    const int pr = (t>>4)*2, pc = (t&15)*4;
    for (int sq=0; sq<3; sq++){
      float4 ac0=make_float4(0,0,0,0), ac1=ac0;
      #pragma unroll 4
      for (int q=0;q<64;q++){
        float4 bv = *(const float4*)(sA + q*64 + pc);
        float a0=sA[pr*64+q], a1=sA[(pr+1)*64+q];
        ac0.x+=a0*bv.x; ac0.y+=a0*bv.y; ac0.z+=a0*bv.z; ac0.w+=a0*bv.w;
        ac1.x+=a1*bv.x; ac1.y+=a1*bv.y; ac1.z+=a1*bv.z; ac1.w+=a1*bv.w;
      }
      *(float4*)(sB + (pr+0)*64 + pc) = ac0;
      *(float4*)(sB + (pr+1)*64 + pc) = ac1;
      __syncthreads();
      #pragma unroll
      for (int k=0;k<2;k++) ((float4*)sA)[t*2+k] = ((const float4*)sB)[t*2+k];
      __syncthreads();
    }
    if (t < 32){
      sv[lane]=1.f; sv[lane+32]=1.f; __syncwarp();
      for (int it=0; it<10; it++){
        float y0=0.f, y1=0.f;
        for (int q=0;q<64;q++){ float vq=sv[q]; y0+=sA[q*64+lane]*vq; y1+=sA[q*64+32+lane]*vq; }
        float rn = rsqrtf(wsum(y0*y0+y1*y1));
        sv[lane]=y0*rn; sv[lane+32]=y1*rn; __syncwarp();
      }
      float p0=0.f, p1=0.f;     // Rayleigh on ORIGINAL G
      for (int q=0;q<64;q++){ float vq=sv[q]; p0+=g_G[lane*64+q]*vq; p1+=g_G[(lane+32)*64+q]*vq; }
      float lam = wsum(p0*sv[lane]+p1*sv[lane+32]);
      if (!lane) g_inv_sigma = 1.f/fmaxf(sqrtf(fmaxf(lam,0.f)),1e-8f);
    }
    return;
  }
  if (blk == 1){                  // anchor columns of y0 (cols 48-95)
    for (int idx=t; idx<3072; idx+=512){
      int i = idx/48, c = idx - i*48;
      g_M4[i*NC + 48 + c] = (c<16)? acanch[c*ND+i] : canch[(c-16)*ND+i];
    }
    return;
  }
  if (blk == 2){                  // g_bz row + u1/u2 columns
    for (int idx=t; idx<4*NC; idx+=512) g_bz[idx] = 0.f;
    __syncthreads();
    for (int j=w; j<178; j+=16){
      if (j < 48){
        const float* B = (j<16)? g_AKC+j*NDM : g_KC+(j-16)*NDM;
        float s = dot256(g_B6, B, lane);
        if (!lane) g_bz[j] = s;
      } else if (j < 50){
        const float* B = (j==48)? g_B6+NDM : g_B6+3*NDM;
        float s = dot256(g_B6, B, lane);
        if (!lane) g_bz[(j==48)?96:97] = s;
      } else if (j < 114){
        int i = j-50;
        float s = dot256(Zq+i*NDM, g_B6+NDM, lane);
        if (!lane) g_M4[i*NC+96] = s;
      } else {
        int i = j-114;
        float s = dot256(Zq+i*NDM, g_B6+3*NDM, lane);
        if (!lane) g_M4[i*NC+97] = s;
      }
    }
    return;
  }
  if (blk == 3){                  // w1,w2 (col 128) and vb3,vb4 (cols 48/49 of y3)
    for (int j=w; j<256; j+=16){
      float s; int r, col;
      if (j < 64)      { s = dot256(Lk+j*NDM,          g_B6,       lane); r=64+j;        col=128; }
      else if (j<128)  { s = dot256(Ck+(j-64)*NDM,     g_B6,       lane); r=128+(j-64);  col=128; }
      else if (j<192)  { s = dot256(g_M2T2+(j-128)*NDM,g_B6+2*NDM, lane); r=192+(j-128); col=48;  }
      else             { s = dot256(g_M2T2+(j-192)*NDM,g_B6+4*NDM, lane); r=192+(j-192); col=49;  }
      if (!lane) g_M4[r*NC+col] = s;
    }
    return;
  }
  // ---- tile blocks 4..27: 32x32 stage-2 GEMM tiles, B transposed-access ----
  {
    int tid = blk - 4;            // 0..23
    int typ = tid>>2, sub = tid&3, m0 = (sub>>1)*32, n0 = (sub&1)*32;
    const float* Ab; int orow, ocol, maxc, bsel;
    switch(typ){
      case 0: Ab=Zq;     orow=0;   ocol=0;  maxc=48; bsel=0; break;
      case 1: Ab=Lk;     orow=64;  ocol=0;  maxc=64; bsel=1; break;
      case 2: Ab=Lv;     orow=64;  ocol=64; maxc=64; bsel=2; break;
      case 3: Ab=Ck;     orow=128; ocol=0;  maxc=64; bsel=1; break;
      case 4: Ab=Cv;     orow=128; ocol=64; maxc=64; bsel=2; break;
      default:Ab=g_M2T2; orow=192; ocol=0;  maxc=48; bsel=3; break;
    }
    float* As = sm; float* Bs = sm + 2080;
    const int r2 = t>>4, kg = (t&15)*4;
    const float* Ap = Ab + (m0+r2)*NDM;
    const int cB = t>>4, kg2 = (t&15)*4;
    int cglob = n0 + cB;
    const float* Bp;
    if (bsel==0)      Bp = (cglob<16)? g_AKC + cglob*NDM : (cglob<48)? g_KC + (cglob-16)*NDM : g_AKC;
    else if (bsel==1) Bp = g_M5 + cglob*NDM;
    else if (bsel==2) Bp = g_M2T2 + cglob*NDM;
    else              Bp = (cglob<16)? g_AVC + cglob*NDM : (cglob<48)? g_VC + (cglob-16)*NDM : g_AVC;

    float4 apf, bpf;
    auto loadA  = [&](int k0){ apf = *(const float4*)(Ap + k0 + kg); };
    auto storeA = [&](){
      float* a = As + r2*65 + kg;
      a[0]=apf.x; a[1]=apf.y; a[2]=apf.z; a[3]=apf.w;
    };
    auto loadB  = [&](int k0){ bpf = *(const float4*)(Bp + k0 + kg2); };
    auto storeB = [&](){
      const float* bv = (const float*)&bpf;
      #pragma unroll
      for (int i=0;i<4;i++){
        int kk = kg2+i;
        Bs[kk*36 + (cB ^ (((kk>>2)&7)<<2))] = bv[i];
      }
    };

    float acc0=0.f, acc1=0.f;
    const int cw = w*2;
    auto compute = [&](){
      #pragma unroll 8
      for (int kk=0;kk<64;kk++){
        float av = As[lane*65+kk];
        int pc = cw ^ (((kk>>2)&7)<<2);
        float2 bv = *(const float2*)(Bs + kk*36 + pc);
        acc0 += av*bv.x; acc1 += av*bv.y;
      }
    };

    loadA(0); loadB(0); storeA(); storeB(); __syncthreads();
    #pragma unroll 1
    for (int c=1;c<4;c++){
      loadA(c*64); loadB(c*64);
      compute(); __syncthreads();
      storeA(); storeB(); __syncthreads();
    }
    compute();

    int j0 = n0 + cw;
    int row = orow + m0 + lane;
    if (j0   < maxc) g_M4[row*NC + ocol + j0    ] = acc0;
    if (j0+1 < maxc) g_M4[row*NC + ocol + j0 + 1] = acc1;
  }
}

// =============== GF: fused ceff + GEMM-tile + attention + epilogue ===============
#define SG_STRIDE 416   // col offsets: y0=0 (98), y1=98 (129), y2=227 (129), y3=356 (50)
__global__ __launch_bounds__(512) void gf_kernel(
  const float* __restrict__ z,   const float* __restrict__ rw,
  const float* __restrict__ az,  const float* __restrict__ arw,
  const float* __restrict__ acz, const float* __restrict__ ctrl,
  const float* __restrict__ ecov,const float* __restrict__ formb,
  float* __restrict__ out)
{
  __shared__ __align__(16) float xsT[4*64*20];        // [y][i][bb], bb stride 20
  __shared__ float sg[16*SG_STRIDE];                  // [bat][col]
  const int t = threadIdx.x;
  const int b0 = blockIdx.x*16;
  const int w = t>>5, lane = t&31;
  const int b = b0 + w;

  for (int idx=t; idx<3072; idx+=512){
    int y = idx>>10, r = idx&1023, bb = r>>6, i = r&63;
    const float* X = (y==0)? z : (y==1)? az : acz;
    xsT[(y*64+i)*20 + bb] = X[(b0+bb)*ND + i];
  }

  float e0=ecov[b*ND+lane], e1=ecov[b*ND+32+lane];
  float c0g=ctrl[b*ND+lane], c1g=ctrl[b*ND+32+lane];
  float ee = wsum(e0*e0+e1*e1);
  float ec = wsum(e0*c0g+e1*c1g);
  float kk = (ee > 1e-8f) ? ec/fmaxf(ee,1e-8f) : 0.f;
  float ce0 = c0g - kk*e0, ce1 = c1g - kk*e1;
  float fb = wsum(formb[lane]*ce0 + formb[lane+32]*ce1);
  xsT[(3*64+lane)*20 + w]    = ce0;
  xsT[(3*64+32+lane)*20 + w] = ce1;
  __syncthreads();

  if (t < 406){
    int y, col;
    if (t<98){y=0;col=t;} else if (t<227){y=1;col=t-98;}
    else if (t<356){y=2;col=t-227;} else {y=3;col=t-356;}
    const float* M  = g_M4 + (y*ND)*NC + col;
    const float* xb = xsT + (y*64)*20;
    float a0=0,a1=0,a2=0,a3=0,a4=0,a5=0,a6=0,a7=0,a8=0,a9=0,aa=0,ab=0,ac=0,ad=0,ae=0,af=0;
    #pragma unroll 4
    for (int i=0;i<64;i++){
      float mv = M[(size_t)i*NC];
      const float4* x4 = (const float4*)(xb + i*20);
      float4 v0=x4[0], v1=x4[1], v2=x4[2], v3=x4[3];
      a0+=mv*v0.x; a1+=mv*v0.y; a2+=mv*v0.z; a3+=mv*v0.w;
      a4+=mv*v1.x; a5+=mv*v1.y; a6+=mv*v1.z; a7+=mv*v1.w;
      a8+=mv*v2.x; a9+=mv*v2.y; aa+=mv*v2.z; ab+=mv*v2.w;
      ac+=mv*v3.x; ad+=mv*v3.y; ae+=mv*v3.z; af+=mv*v3.w;
    }
    float bz = g_bz[y*NC+col];
    sg[ 0*SG_STRIDE+t]=a0+bz; sg[ 1*SG_STRIDE+t]=a1+bz;
    sg[ 2*SG_STRIDE+t]=a2+bz; sg[ 3*SG_STRIDE+t]=a3+bz;
    sg[ 4*SG_STRIDE+t]=a4+bz; sg[ 5*SG_STRIDE+t]=a5+bz;
    sg[ 6*SG_STRIDE+t]=a6+bz; sg[ 7*SG_STRIDE+t]=a7+bz;
    sg[ 8*SG_STRIDE+t]=a8+bz; sg[ 9*SG_STRIDE+t]=a9+bz;
    sg[10*SG_STRIDE+t]=aa+bz; sg[11*SG_STRIDE+t]=ab+bz;
    sg[12*SG_STRIDE+t]=ac+bz; sg[13*SG_STRIDE+t]=ad+bz;
    sg[14*SG_STRIDE+t]=ae+bz; sg[15*SG_STRIDE+t]=af+bz;
  }
  __syncthreads();

  const float* gz   = sg + w*SG_STRIDE;
  const float* gaz  = gz + 98;
  const float* gacz = gz + 227;
  const float* gc   = gz + 356;

  float z0  = z[b*ND+lane],   z1  = z[b*ND+32+lane];
  float a0  = az[b*ND+lane],  a1  = az[b*ND+32+lane];
  float c0  = acz[b*ND+lane], c1  = acz[b*ND+32+lane];

  float d_z2   = wsum(z0*z0 + z1*z1);
  float d_zaz  = wsum(z0*a0 + z1*a1);
  float d_az2  = wsum(a0*a0 + a1*a1);
  float d_zacz = wsum(z0*c0 + z1*c1);
  float d_acz2 = wsum(c0*c0 + c1*c1);
  float d_zy1  = wsum(z0*gaz[lane]     + z1*gaz[32+lane]);
  float d_zy2  = wsum(z0*gacz[lane]    + z1*gacz[32+lane]);
  float d_cy3  = wsum(ce0*gaz[64+lane] + ce1*gaz[96+lane]);
  float d_cy4  = wsum(ce0*gacz[64+lane]+ ce1*gacz[96+lane]);

  float s0, t0, s1 = -1e30f, t1 = 0.f;
  {
    int tok = lane;
    if (tok == 0){
      s0 = (d_zy1 + gz[96] + gaz[128])*0.0625f - (d_z2 - 2.f*d_zaz + d_az2);
      t0 = d_cy3 + gc[48];
    } else if (tok == 1){
      s0 = (d_zy2 + gz[97] + gacz[128])*0.0625f - (d_z2 - 2.f*d_zacz + d_acz2);
      t0 = d_cy4 + gc[49];
    } else if (tok < 18){
      int k = tok-2; float aw = arw[b*NKA+k];
      s0 = aw*gz[k]*0.0625f - (d_z2 - 2.f*gz[48+k] + g_aan2[k]);
      t0 = aw*gc[k];
    } else {
      int k = tok-18; float cw = rw[b*NK+k];
      s0 = cw*gz[16+k]*0.0625f - (d_z2 - 2.f*gz[64+k] + g_an2[k]);
      t0 = cw*gc[16+k];
    }
  }
  if (lane < 18){
    int k = lane + 14;
    float cw = rw[b*NK+k];
    s1 = cw*gz[16+k]*0.0625f - (d_z2 - 2.f*gz[64+k] + g_an2[k]);
    t1 = cw*gc[16+k];
  }

  float m = wmax(fmaxf(s0, s1));
  float ex0 = __expf(s0 - m);
  float ex1 = (lane < 18) ? __expf(s1 - m) : 0.f;
  float den = wsum(ex0 + ex1);
  float num = wsum(ex0*t0 + ex1*t1);
  if (!lane) out[b] = g_inv_sigma * num / den + fb;
}

// =============== launch ===============
extern "C" void kernel_launch(void* const* d_in, const int* in_sizes, int n_in,
                              void* d_out, int out_size)
{
  const float* z     =(const float*)d_in[0];
  const float* rw    =(const float*)d_in[1];
  const float* az    =(const float*)d_in[2];
  const float* arw   =(const float*)d_in[3];
  const float* acz   =(const float*)d_in[4];
  const float* ctrl  =(const float*)d_in[5];
  const float* ecov  =(const float*)d_in[6];
  const float* cemb  =(const float*)d_in[7];
  const float* canch =(const float*)d_in[8];
  const float* acemb =(const float*)d_in[9];
  const float* acanch=(const float*)d_in[10];
  const float* zW    =(const float*)d_in[11];
  const float* zb    =(const float*)d_in[12];
  const float* latW  =(const float*)d_in[13];
  const float* latb  =(const float*)d_in[14];
  const float* codeW =(const float*)d_in[15];
  const float* codeb =(const float*)d_in[16];
  const float* Wq    =(const float*)d_in[17];
  const float* Wk    =(const float*)d_in[18];
  const float* Wv    =(const float*)d_in[19];
  const float* Wo    =(const float*)d_in[20];
  const float* formW =(const float*)d_in[21];
  const float* formb =(const float*)d_in[22];
  float* out = (float*)d_out;

  p_kernel<<<138,512>>>(zW,latW,codeW,Wq,Wk,Wv,Wo,cemb,acemb,formW,
                        zb,latb,codeb,canch,acanch);
  p2s_kernel<<<28,512>>>(canch,acanch);
  gf_kernel<<<256,512>>>(z,rw,az,arw,acz,ctrl,ecov,formb,out);
}